// round 1
// baseline (speedup 1.0000x reference)
#include <cuda_runtime.h>
#include <cstdint>
#include <math.h>

// Problem constants
#define B_SZ 1024
#define D_SZ 512
#define H_SZ 1024
#define T_SZ 8
#define E_SZ 18

// ---------------- scratch (static device globals; no allocation) ----------------
__device__ float g_H1[B_SZ * E_SZ * H_SZ];   // (B,18,H)  75.5 MB
__device__ float g_EO[B_SZ * E_SZ * D_SZ];   // (B,18,D)  37.7 MB
__device__ float g_X1[B_SZ * 9 * D_SZ];      // (B,9,D)   18.9 MB
__device__ float g_G [B_SZ * 9 * E_SZ];      // (B,9,18)

// ---------------- helpers ----------------
__device__ __forceinline__ float2 u2f2(uint64_t u) {
    float2 f;
    f.x = __uint_as_float((uint32_t)u);
    f.y = __uint_as_float((uint32_t)(u >> 32));
    return f;
}

// ---------------- batched-expert GEMM: C = act(A @ W[e] + bias[e]) -------------
// A row (m, e) at A + (e>>a_e_shift)*a_e_stride + m*a_row_stride, length K
// W: (E, K, N) row-major.  C element (m, e, n) at C + e*N + m*c_row_stride + n.
// Tile 128x128x16, 256 threads, 8x8 per thread, fma.rn.f32x2 packed math.
#define BM 128
#define BN 128
#define BK 16

template<int RELU>
__global__ __launch_bounds__(256, 2)
void gemm_expert(const float* __restrict__ A,
                 const float* __restrict__ W,
                 const float* __restrict__ bias,
                 float* __restrict__ C,
                 int M, int N, int K,
                 int a_row_stride, int a_e_shift, int a_e_stride,
                 int c_row_stride)
{
    __shared__ float As2[BK][2 * BM];   // A duplicated: As2[k][2m]=As2[k][2m+1]=A[m][k]
    __shared__ float Bs[BK][BN];

    const int e  = blockIdx.z;
    const int m0 = blockIdx.y * BM;
    const int n0 = blockIdx.x * BN;

    const float* Ae = A + (size_t)(e >> a_e_shift) * a_e_stride;
    const float* We = W + (size_t)e * K * N;
    float*       Ce = C + (size_t)e * N;

    const int tid = threadIdx.x;
    const int tx  = tid & 15;   // n direction
    const int ty  = tid >> 4;   // m direction

    uint64_t acc[8][4];
    #pragma unroll
    for (int i = 0; i < 8; i++)
        #pragma unroll
        for (int j = 0; j < 4; j++)
            acc[i][j] = 0ull;  // (0.0f, 0.0f)

    const int nk = K >> 4;
    for (int kt = 0; kt < nk; ++kt) {
        // ---- load tiles ----
        #pragma unroll
        for (int t = 0; t < 2; t++) {
            int idx = t * 256 + tid;
            // A: 128 rows x 16 k  (512 float4)
            int am = idx >> 2, ak4 = idx & 3;
            const float4 va = *(const float4*)(Ae + (size_t)(m0 + am) * a_row_stride
                                               + kt * BK + ak4 * 4);
            *(float2*)&As2[ak4 * 4 + 0][2 * am] = make_float2(va.x, va.x);
            *(float2*)&As2[ak4 * 4 + 1][2 * am] = make_float2(va.y, va.y);
            *(float2*)&As2[ak4 * 4 + 2][2 * am] = make_float2(va.z, va.z);
            *(float2*)&As2[ak4 * 4 + 3][2 * am] = make_float2(va.w, va.w);
            // B: 16 k x 128 n (512 float4)
            int bn4 = idx & 31, bk = idx >> 5;
            const float4 vb = *(const float4*)(We + (size_t)(kt * BK + bk) * N
                                               + n0 + bn4 * 4);
            *(float4*)&Bs[bk][bn4 * 4] = vb;
        }
        __syncthreads();

        // ---- compute ----
        #pragma unroll
        for (int k = 0; k < BK; k++) {
            uint64_t pa[8];
            #pragma unroll
            for (int i = 0; i < 8; i++)
                pa[i] = *(const uint64_t*)&As2[k][(ty * 8 + i) * 2];
            const ulonglong2* bp = (const ulonglong2*)&Bs[k][tx * 8];
            ulonglong2 q0 = bp[0];
            ulonglong2 q1 = bp[1];
            uint64_t pb[4];
            pb[0] = q0.x; pb[1] = q0.y; pb[2] = q1.x; pb[3] = q1.y;
            #pragma unroll
            for (int i = 0; i < 8; i++)
                #pragma unroll
                for (int j = 0; j < 4; j++)
                    asm("fma.rn.f32x2 %0, %1, %2, %0;"
                        : "+l"(acc[i][j]) : "l"(pa[i]), "l"(pb[j]));
        }
        __syncthreads();
    }

    // ---- epilogue: bias (+relu), write ----
    const float* be = bias + (size_t)e * N;
    #pragma unroll
    for (int i = 0; i < 8; i++) {
        int m = m0 + ty * 8 + i;
        float* crow = Ce + (size_t)m * c_row_stride;
        #pragma unroll
        for (int j = 0; j < 4; j++) {
            int n = n0 + tx * 8 + 2 * j;
            float2 v  = u2f2(acc[i][j]);
            float2 bv = *(const float2*)&be[n];
            v.x += bv.x; v.y += bv.y;
            if (RELU) { v.x = fmaxf(v.x, 0.f); v.y = fmaxf(v.y, 0.f); }
            *(float2*)&crow[n] = v;
        }
    }
}

// ---------------- gate: softmax(x[:, :M] @ Wg + bg) + add ----------------------
// One warp per (b, m). x is (B, 9, D). Wg (M, D, E), bg (M, E). G out (B, M, E).
__global__ __launch_bounds__(256)
void gate_kernel(const float* __restrict__ x,
                 const float* __restrict__ Wg,
                 const float* __restrict__ bg,
                 const float* __restrict__ sew_task,   // (T, 2, 2)
                 const float* __restrict__ sew_shared, // (1, 2)
                 float* __restrict__ G,
                 int M, int layer)
{
    __shared__ float xs[8][D_SZ];
    const int wl   = threadIdx.x >> 5;
    const int lane = threadIdx.x & 31;
    const int wg   = blockIdx.x * 8 + wl;
    if (wg >= B_SZ * M) return;
    const int b = wg / M;
    const int m = wg - b * M;

    const float* xr = x + ((size_t)b * 9 + m) * D_SZ;
    for (int k = lane; k < D_SZ; k += 32) xs[wl][k] = xr[k];
    __syncwarp();

    float acc = 0.f;
    if (lane < E_SZ) {
        const float* w = Wg + (size_t)m * D_SZ * E_SZ + lane;
        #pragma unroll 4
        for (int k = 0; k < D_SZ; k++)
            acc += xs[wl][k] * w[(size_t)k * E_SZ];
        acc += bg[m * E_SZ + lane];
    }
    float v = (lane < E_SZ) ? acc : -3.4e38f;
    float mx = v;
    #pragma unroll
    for (int o = 16; o > 0; o >>= 1)
        mx = fmaxf(mx, __shfl_xor_sync(0xffffffffu, mx, o));
    float ex = (lane < E_SZ) ? expf(v - mx) : 0.f;
    float s = ex;
    #pragma unroll
    for (int o = 16; o > 0; o >>= 1)
        s += __shfl_xor_sync(0xffffffffu, s, o);

    if (lane < E_SZ) {
        float g = ex / s;
        float addv = 0.f;
        if (layer == 0) {
            if (m < T_SZ && (lane >> 1) == m) addv = sew_task[m * 4 + (lane & 1)];
            if (m == T_SZ && lane >= 16)      addv = sew_shared[lane - 16];
        } else {
            if ((lane >> 1) == m)             addv = sew_task[m * 4 + 2 + (lane & 1)];
        }
        G[((size_t)b * M + m) * E_SZ + lane] = g + addv;
    }
}

// ---------------- combine: out[b,m,:] = sum_e G[b,m,e] * EO[b,e,:] -------------
__global__ __launch_bounds__(256)
void combine_kernel(const float* __restrict__ EO,
                    const float* __restrict__ G,
                    float* __restrict__ OUT,
                    int M)
{
    __shared__ float gs[9 * E_SZ];
    const int b   = blockIdx.x;
    const int tid = threadIdx.x;
    if (tid < M * E_SZ) gs[tid] = G[(size_t)b * M * E_SZ + tid];
    __syncthreads();

    const float* eo = EO + (size_t)b * E_SZ * D_SZ;
    for (int d = tid; d < D_SZ; d += 256) {
        float ev[E_SZ];
        #pragma unroll
        for (int e2 = 0; e2 < E_SZ; e2++)
            ev[e2] = eo[(size_t)e2 * D_SZ + d];
        for (int m = 0; m < M; m++) {
            float s = 0.f;
            #pragma unroll
            for (int e2 = 0; e2 < E_SZ; e2++)
                s += gs[m * E_SZ + e2] * ev[e2];
            OUT[((size_t)b * M + m) * D_SZ + d] = s;
        }
    }
}

// ---------------- launcher ----------------
extern "C" void kernel_launch(void* const* d_in, const int* in_sizes, int n_in,
                              void* d_out, int out_size)
{
    const float* x_in  = (const float*)d_in[0];
    const float* W1_0  = (const float*)d_in[1];
    const float* b1_0  = (const float*)d_in[2];
    const float* W2_0  = (const float*)d_in[3];
    const float* b2_0  = (const float*)d_in[4];
    const float* Wg_0  = (const float*)d_in[5];
    const float* bg_0  = (const float*)d_in[6];
    const float* W1_1  = (const float*)d_in[7];
    const float* b1_1  = (const float*)d_in[8];
    const float* W2_1  = (const float*)d_in[9];
    const float* b2_1  = (const float*)d_in[10];
    const float* Wg_1  = (const float*)d_in[11];
    const float* bg_1  = (const float*)d_in[12];
    const float* sewt  = (const float*)d_in[13];
    const float* sews  = (const float*)d_in[14];
    float* out = (float*)d_out;

    float *H1p, *EOp, *X1p, *Gp;
    cudaGetSymbolAddress((void**)&H1p, g_H1);
    cudaGetSymbolAddress((void**)&EOp, g_EO);
    cudaGetSymbolAddress((void**)&X1p, g_X1);
    cudaGetSymbolAddress((void**)&Gp,  g_G);

    dim3 gFF1(H_SZ / BN, B_SZ / BM, E_SZ);   // (8, 8, 18)
    dim3 gFF2(D_SZ / BN, B_SZ / BM, E_SZ);   // (4, 8, 18)

    // -------- layer 0 --------
    gemm_expert<1><<<gFF1, 256>>>(x_in, W1_0, b1_0, H1p,
                                  B_SZ, H_SZ, D_SZ,
                                  9 * D_SZ, 1, D_SZ, E_SZ * H_SZ);
    gemm_expert<0><<<gFF2, 256>>>(H1p, W2_0, b2_0, EOp,
                                  B_SZ, D_SZ, H_SZ,
                                  E_SZ * H_SZ, 0, H_SZ, E_SZ * D_SZ);
    gate_kernel<<<(B_SZ * 9 + 7) / 8, 256>>>(x_in, Wg_0, bg_0, sewt, sews, Gp, 9, 0);
    combine_kernel<<<B_SZ, 256>>>(EOp, Gp, X1p, 9);

    // -------- layer 1 --------
    gemm_expert<1><<<gFF1, 256>>>(X1p, W1_1, b1_1, H1p,
                                  B_SZ, H_SZ, D_SZ,
                                  9 * D_SZ, 1, D_SZ, E_SZ * H_SZ);
    gemm_expert<0><<<gFF2, 256>>>(H1p, W2_1, b2_1, EOp,
                                  B_SZ, D_SZ, H_SZ,
                                  E_SZ * H_SZ, 0, H_SZ, E_SZ * D_SZ);
    gate_kernel<<<(B_SZ * 8 + 7) / 8, 256>>>(X1p, Wg_1, bg_1, sewt, sews, Gp, 8, 1);
    combine_kernel<<<B_SZ, 256>>>(EOp, Gp, out, 8);
}

// round 4
// speedup vs baseline: 2.6209x; 2.6209x over previous
#include <cuda_runtime.h>
#include <cuda_bf16.h>
#include <cstdint>
#include <math.h>

// Problem constants
#define B_SZ 1024
#define D_SZ 512
#define H_SZ 1024
#define T_SZ 8
#define E_SZ 18

// ==================== PTX helpers (plain sm_103-safe: mma.sync / ldmatrix / cp.async) ====
__device__ __forceinline__ uint32_t smem_to_u32(const void* p) {
    uint32_t a;
    asm("{ .reg .u64 t; cvta.to.shared.u64 t, %1; cvt.u32.u64 %0, t; }" : "=r"(a) : "l"(p));
    return a;
}
#define CP_ASYNC16(dst, src) \
    asm volatile("cp.async.cg.shared.global [%0], [%1], 16;" :: "r"(dst), "l"(src))
#define CP_COMMIT() asm volatile("cp.async.commit_group;" ::: "memory")
#define CP_WAIT1()  asm volatile("cp.async.wait_group 1;" ::: "memory")

#define LDSM_X4(r, a) \
    asm volatile("ldmatrix.sync.aligned.m8n8.x4.shared.b16 {%0,%1,%2,%3}, [%4];" \
        : "=r"((r)[0]), "=r"((r)[1]), "=r"((r)[2]), "=r"((r)[3]) : "r"(a))
#define LDSM_X4T(r, a) \
    asm volatile("ldmatrix.sync.aligned.m8n8.x4.trans.shared.b16 {%0,%1,%2,%3}, [%4];" \
        : "=r"((r)[0]), "=r"((r)[1]), "=r"((r)[2]), "=r"((r)[3]) : "r"(a))

#define MMA16816(c, a, b0, b1) \
    asm volatile("mma.sync.aligned.m16n8k16.row.col.f32.bf16.bf16.f32 " \
        "{%0,%1,%2,%3}, {%4,%5,%6,%7}, {%8,%9}, {%0,%1,%2,%3};" \
        : "+f"((c)[0]), "+f"((c)[1]), "+f"((c)[2]), "+f"((c)[3]) \
        : "r"((a)[0]), "r"((a)[1]), "r"((a)[2]), "r"((a)[3]), "r"(b0), "r"(b1))

// ==================== scratch (static device globals) ====================
__device__ __nv_bfloat16 g_xh [B_SZ * 9 * D_SZ];
__device__ __nv_bfloat16 g_xl [B_SZ * 9 * D_SZ];
#define WT_ONE (E_SZ * H_SZ * D_SZ)            // 9,437,184 elems per weight tensor
__device__ __nv_bfloat16 g_wh[4 * WT_ONE];     // (E,K,N) native layout hi: W1_0,W2_0,W1_1,W2_1
__device__ __nv_bfloat16 g_wl[4 * WT_ONE];
__device__ __nv_bfloat16 g_h1h[B_SZ * E_SZ * H_SZ];
__device__ __nv_bfloat16 g_h1l[B_SZ * E_SZ * H_SZ];
__device__ float         g_eo [B_SZ * E_SZ * D_SZ];
__device__ float         g_x1 [B_SZ * 9 * D_SZ];
__device__ __nv_bfloat16 g_x1h[B_SZ * 9 * D_SZ];
__device__ __nv_bfloat16 g_x1l[B_SZ * 9 * D_SZ];
__device__ float         g_G  [B_SZ * 9 * E_SZ];

// ==================== prep: fp32 -> bf16 hi/lo split (elementwise) ====================
__global__ __launch_bounds__(256)
void split_f32(const float* __restrict__ X, __nv_bfloat16* __restrict__ H,
               __nv_bfloat16* __restrict__ L, int n4)
{
    int i = blockIdx.x * blockDim.x + threadIdx.x;
    if (i >= n4) return;
    float4 v = ((const float4*)X)[i];
    __nv_bfloat16 h0 = __float2bfloat16(v.x), h1 = __float2bfloat16(v.y);
    __nv_bfloat16 h2 = __float2bfloat16(v.z), h3 = __float2bfloat16(v.w);
    __nv_bfloat162 hp0 = {h0, h1}, hp1 = {h2, h3};
    __nv_bfloat162 lp0 = {__float2bfloat16(v.x - __bfloat162float(h0)),
                          __float2bfloat16(v.y - __bfloat162float(h1))};
    __nv_bfloat162 lp1 = {__float2bfloat16(v.z - __bfloat162float(h2)),
                          __float2bfloat16(v.w - __bfloat162float(h3))};
    ((__nv_bfloat162*)H)[2*i]   = hp0; ((__nv_bfloat162*)H)[2*i+1] = hp1;
    ((__nv_bfloat162*)L)[2*i]   = lp0; ((__nv_bfloat162*)L)[2*i+1] = lp1;
}

// ==================== GEMM: mma.sync bf16 3-term split ====================
// C[m,e,n] (pitch 18*Ntot) = act( sum_k A[(m*a_mul+(e>>a_shift)), k] * W[e, k, n] + bias[e,n] )
// A: k-major rows (hi/lo). W: (E, K, N) native n-major rows (hi/lo), consumed via ldmatrix.trans.
// 128x128 tile, BK=32, 3-stage cp.async pipeline, 8 warps (4m x 2n), warp tile 32x64.
#define STAGE_BYTES 32768
#define GEMM_SMEM   (1024 + 3 * STAGE_BYTES)

template<int EPI_BF16>
__global__ __launch_bounds__(256, 1)
void gemm_mma3(const __nv_bfloat16* __restrict__ Ah, const __nv_bfloat16* __restrict__ Al,
               const __nv_bfloat16* __restrict__ Bh, const __nv_bfloat16* __restrict__ Bl,
               const float* __restrict__ bias,
               float* __restrict__ Cf, __nv_bfloat16* __restrict__ Ch,
               __nv_bfloat16* __restrict__ Cl,
               int K, int a_mul, int a_shift, int Ntot)
{
    extern __shared__ char smem[];
    const uint32_t su = smem_to_u32(smem);
    const int tid  = threadIdx.x;
    const int wid  = tid >> 5;
    const int lane = tid & 31;
    const int e  = blockIdx.z;
    const int m0 = blockIdx.y * 128;
    const int n0 = blockIdx.x * 128;
    const int warp_m = wid & 3;     // 4 warps in m
    const int warp_n = wid >> 2;    // 2 warps in n
    const int esel = e >> a_shift;

    // bias -> smem [0..511]
    if (tid < 128)
        ((float*)smem)[tid] = bias[(size_t)e * Ntot + n0 + tid];

    // ---- stage loader (cp.async) ----
    // A tile: 128 rows x 32 k (64B rows, 4 chunks), swizzle c ^ ((m>>1)&3)
    // B tile: 32 k-rows x 128 n (256B rows, 16 chunks), swizzle c ^ (k&7)
    auto load_stage = [&](int s, int k0) {
        uint32_t st = su + 1024 + s * STAGE_BYTES;
        #pragma unroll
        for (int t = 0; t < 2; ++t) {
            int idx = tid + t * 256;
            int arow = idx >> 2, ac = idx & 3;
            size_t aoff = ((size_t)(m0 + arow) * a_mul + esel) * K + k0 + ac * 8;
            uint32_t ad = arow * 64 + ((ac ^ ((arow >> 1) & 3)) << 4);
            CP_ASYNC16(st + ad,        Ah + aoff);
            CP_ASYNC16(st + 8192 + ad, Al + aoff);
            int krow = idx >> 4, nc = idx & 15;
            size_t boff = ((size_t)e * K + k0 + krow) * Ntot + n0 + nc * 8;
            uint32_t bd = krow * 256 + ((nc ^ (krow & 7)) << 4);
            CP_ASYNC16(st + 16384 + bd, Bh + boff);
            CP_ASYNC16(st + 24576 + bd, Bl + boff);
        }
        CP_COMMIT();
    };

    float c[2][8][4];
    #pragma unroll
    for (int i = 0; i < 2; i++)
        #pragma unroll
        for (int j = 0; j < 8; j++)
            #pragma unroll
            for (int q = 0; q < 4; q++) c[i][j][q] = 0.f;

    const int nk = K >> 5;
    load_stage(0, 0);
    load_stage(1, 32);

    // precomputed ldmatrix address components
    const int a_rl   = (lane & 7) + ((lane >> 3) & 1) * 8;  // row within 16-row frag
    const int a_kc_h = lane >> 4;                           // 0/1: k chunk half
    const int b_kl   = (lane & 7) + ((lane >> 3) & 1) * 8;  // k row within 16
    const int b_nc_h = lane >> 4;                           // 0/1: n chunk half

    int s = 0;
    for (int cIt = 0; cIt < nk; ++cIt) {
        CP_WAIT1();
        __syncthreads();
        if (cIt + 2 < nk) {
            int sn = s + 2;
            if (sn >= 3) sn -= 3;                 // FIX: proper mod-3 stage rotation
            load_stage(sn, (cIt + 2) << 5);
        } else {
            CP_COMMIT();
        }

        uint32_t st = su + 1024 + s * STAGE_BYTES;
        #pragma unroll
        for (int ks = 0; ks < 2; ++ks) {
            uint32_t ah[2][4], al[2][4];
            #pragma unroll
            for (int mi = 0; mi < 2; ++mi) {
                int row = warp_m * 32 + mi * 16 + a_rl;
                int kc  = ks * 2 + a_kc_h;
                uint32_t ad = st + row * 64 + ((kc ^ ((row >> 1) & 3)) << 4);
                LDSM_X4(ah[mi], ad);
                LDSM_X4(al[mi], ad + 8192);
            }
            uint32_t bh[4][4], bl[4][4];
            #pragma unroll
            for (int ni = 0; ni < 4; ++ni) {
                int krow = ks * 16 + b_kl;
                int nc   = warp_n * 8 + ni * 2 + b_nc_h;
                uint32_t bd = st + 16384 + krow * 256 + ((nc ^ (krow & 7)) << 4);
                LDSM_X4T(bh[ni], bd);
                LDSM_X4T(bl[ni], bd + 8192);
            }
            #pragma unroll
            for (int mi = 0; mi < 2; ++mi)
                #pragma unroll
                for (int ni = 0; ni < 4; ++ni)
                    #pragma unroll
                    for (int h = 0; h < 2; ++h) {
                        float* cc = c[mi][ni * 2 + h];
                        uint32_t bh0 = bh[ni][h * 2], bh1 = bh[ni][h * 2 + 1];
                        uint32_t bl0 = bl[ni][h * 2], bl1 = bl[ni][h * 2 + 1];
                        MMA16816(cc, ah[mi], bh0, bh1);
                        MMA16816(cc, ah[mi], bl0, bl1);
                        MMA16816(cc, al[mi], bh0, bh1);
                    }
        }
        __syncthreads();
        s = (s == 2) ? 0 : s + 1;
    }

    // ---- epilogue ----
    const float* bs = (const float*)smem;
    #pragma unroll
    for (int mi = 0; mi < 2; ++mi) {
        int r0 = m0 + warp_m * 32 + mi * 16 + (lane >> 2);
        #pragma unroll
        for (int h2 = 0; h2 < 2; ++h2) {
            int row = r0 + h2 * 8;
            size_t cbase = ((size_t)row * E_SZ + e) * Ntot;
            #pragma unroll
            for (int nj = 0; nj < 8; ++nj) {
                int col = warp_n * 64 + nj * 8 + (lane & 3) * 2;   // relative to n0
                float v0 = c[mi][nj][h2 * 2]     + bs[col];
                float v1 = c[mi][nj][h2 * 2 + 1] + bs[col + 1];
                if (EPI_BF16) {
                    v0 = fmaxf(v0, 0.f); v1 = fmaxf(v1, 0.f);
                    __nv_bfloat16 hh0 = __float2bfloat16(v0);
                    __nv_bfloat16 hh1 = __float2bfloat16(v1);
                    __nv_bfloat162 hp = {hh0, hh1};
                    __nv_bfloat162 lp = {__float2bfloat16(v0 - __bfloat162float(hh0)),
                                         __float2bfloat16(v1 - __bfloat162float(hh1))};
                    *(uint32_t*)(Ch + cbase + n0 + col) = *(uint32_t*)&hp;
                    *(uint32_t*)(Cl + cbase + n0 + col) = *(uint32_t*)&lp;
                } else {
                    *(float2*)(Cf + cbase + n0 + col) = make_float2(v0, v1);
                }
            }
        }
    }
}

// ==================== gate: softmax(x[:, :M] @ Wg + bg) + add ====================
__global__ __launch_bounds__(256)
void gate_kernel(const float* __restrict__ x,
                 const float* __restrict__ Wg,
                 const float* __restrict__ bg,
                 const float* __restrict__ sew_task,
                 const float* __restrict__ sew_shared,
                 float* __restrict__ G,
                 int M, int layer)
{
    __shared__ float xs[8][D_SZ];
    const int wl   = threadIdx.x >> 5;
    const int lane = threadIdx.x & 31;
    const int wg   = blockIdx.x * 8 + wl;
    if (wg >= B_SZ * M) return;
    const int b = wg / M;
    const int m = wg - b * M;

    const float* xr = x + ((size_t)b * 9 + m) * D_SZ;
    for (int k = lane; k < D_SZ; k += 32) xs[wl][k] = xr[k];
    __syncwarp();

    float acc = 0.f;
    if (lane < E_SZ) {
        const float* w = Wg + (size_t)m * D_SZ * E_SZ + lane;
        #pragma unroll 4
        for (int k = 0; k < D_SZ; k++)
            acc += xs[wl][k] * w[(size_t)k * E_SZ];
        acc += bg[m * E_SZ + lane];
    }
    float v = (lane < E_SZ) ? acc : -3.4e38f;
    float mx = v;
    #pragma unroll
    for (int o = 16; o > 0; o >>= 1)
        mx = fmaxf(mx, __shfl_xor_sync(0xffffffffu, mx, o));
    float ex = (lane < E_SZ) ? expf(v - mx) : 0.f;
    float s = ex;
    #pragma unroll
    for (int o = 16; o > 0; o >>= 1)
        s += __shfl_xor_sync(0xffffffffu, s, o);

    if (lane < E_SZ) {
        float g = ex / s;
        float addv = 0.f;
        if (layer == 0) {
            if (m < T_SZ && (lane >> 1) == m) addv = sew_task[m * 4 + (lane & 1)];
            if (m == T_SZ && lane >= 16)      addv = sew_shared[lane - 16];
        } else {
            if ((lane >> 1) == m)             addv = sew_task[m * 4 + 2 + (lane & 1)];
        }
        G[((size_t)b * M + m) * E_SZ + lane] = g + addv;
    }
}

// ==================== combine: out[b,m,:] = sum_e G[b,m,e] * EO[b,e,:] ====================
__global__ __launch_bounds__(256)
void combine_kernel(const float* __restrict__ EO,
                    const float* __restrict__ G,
                    float* __restrict__ OUT,
                    __nv_bfloat16* __restrict__ OH,
                    __nv_bfloat16* __restrict__ OL,
                    int M)
{
    __shared__ float gs[9 * E_SZ];
    const int b   = blockIdx.x;
    const int tid = threadIdx.x;
    if (tid < M * E_SZ) gs[tid] = G[(size_t)b * M * E_SZ + tid];
    __syncthreads();

    const float* eo = EO + (size_t)b * E_SZ * D_SZ;
    for (int d = tid; d < D_SZ; d += 256) {
        float ev[E_SZ];
        #pragma unroll
        for (int e2 = 0; e2 < E_SZ; e2++)
            ev[e2] = eo[(size_t)e2 * D_SZ + d];
        for (int m = 0; m < M; m++) {
            float s = 0.f;
            #pragma unroll
            for (int e2 = 0; e2 < E_SZ; e2++)
                s += gs[m * E_SZ + e2] * ev[e2];
            if (OH) {
                size_t o = ((size_t)b * 9 + m) * D_SZ + d;   // pitch-9 for layer chaining
                OUT[o] = s;
                __nv_bfloat16 h = __float2bfloat16(s);
                OH[o] = h;
                OL[o] = __float2bfloat16(s - __bfloat162float(h));
            } else {
                OUT[((size_t)b * M + m) * D_SZ + d] = s;     // final (B,8,D) contiguous
            }
        }
    }
}

// ==================== launcher ====================
extern "C" void kernel_launch(void* const* d_in, const int* in_sizes, int n_in,
                              void* d_out, int out_size)
{
    const float* x_in  = (const float*)d_in[0];
    const float* W1_0  = (const float*)d_in[1];
    const float* b1_0  = (const float*)d_in[2];
    const float* W2_0  = (const float*)d_in[3];
    const float* b2_0  = (const float*)d_in[4];
    const float* Wg_0  = (const float*)d_in[5];
    const float* bg_0  = (const float*)d_in[6];
    const float* W1_1  = (const float*)d_in[7];
    const float* b1_1  = (const float*)d_in[8];
    const float* W2_1  = (const float*)d_in[9];
    const float* b2_1  = (const float*)d_in[10];
    const float* Wg_1  = (const float*)d_in[11];
    const float* bg_1  = (const float*)d_in[12];
    const float* sewt  = (const float*)d_in[13];
    const float* sews  = (const float*)d_in[14];
    float* out = (float*)d_out;

    __nv_bfloat16 *xh, *xl, *wh, *wl, *h1h, *h1l, *x1h, *x1l;
    float *eo, *x1, *Gp;
    cudaGetSymbolAddress((void**)&xh,  g_xh);
    cudaGetSymbolAddress((void**)&xl,  g_xl);
    cudaGetSymbolAddress((void**)&wh,  g_wh);
    cudaGetSymbolAddress((void**)&wl,  g_wl);
    cudaGetSymbolAddress((void**)&h1h, g_h1h);
    cudaGetSymbolAddress((void**)&h1l, g_h1l);
    cudaGetSymbolAddress((void**)&eo,  g_eo);
    cudaGetSymbolAddress((void**)&x1,  g_x1);
    cudaGetSymbolAddress((void**)&x1h, g_x1h);
    cudaGetSymbolAddress((void**)&x1l, g_x1l);
    cudaGetSymbolAddress((void**)&Gp,  g_G);

    cudaFuncSetAttribute(gemm_mma3<1>, cudaFuncAttributeMaxDynamicSharedMemorySize, GEMM_SMEM);
    cudaFuncSetAttribute(gemm_mma3<0>, cudaFuncAttributeMaxDynamicSharedMemorySize, GEMM_SMEM);

    // ---- prep: hi/lo splits (weights stay in native (E,K,N) layout) ----
    int n4x = B_SZ * 9 * D_SZ / 4;
    split_f32<<<(n4x + 255) / 256, 256>>>(x_in, xh, xl, n4x);
    int n4w = WT_ONE / 4;
    split_f32<<<(n4w + 255) / 256, 256>>>(W1_0, wh + 0*WT_ONE, wl + 0*WT_ONE, n4w);
    split_f32<<<(n4w + 255) / 256, 256>>>(W2_0, wh + 1*WT_ONE, wl + 1*WT_ONE, n4w);
    split_f32<<<(n4w + 255) / 256, 256>>>(W1_1, wh + 2*WT_ONE, wl + 2*WT_ONE, n4w);
    split_f32<<<(n4w + 255) / 256, 256>>>(W2_1, wh + 3*WT_ONE, wl + 3*WT_ONE, n4w);

    dim3 g1(H_SZ / 128, B_SZ / 128, E_SZ);   // (8, 8, 18)
    dim3 g2(D_SZ / 128, B_SZ / 128, E_SZ);   // (4, 8, 18)

    // ---- layer 0 ----
    gemm_mma3<1><<<g1, 256, GEMM_SMEM>>>(xh, xl, wh + 0*WT_ONE, wl + 0*WT_ONE, b1_0,
                                         nullptr, h1h, h1l, D_SZ, 9, 1, H_SZ);
    gemm_mma3<0><<<g2, 256, GEMM_SMEM>>>(h1h, h1l, wh + 1*WT_ONE, wl + 1*WT_ONE, b2_0,
                                         eo, nullptr, nullptr, H_SZ, E_SZ, 0, D_SZ);
    gate_kernel<<<(B_SZ * 9 + 7) / 8, 256>>>(x_in, Wg_0, bg_0, sewt, sews, Gp, 9, 0);
    combine_kernel<<<B_SZ, 256>>>(eo, Gp, x1, x1h, x1l, 9);

    // ---- layer 1 ----
    gemm_mma3<1><<<g1, 256, GEMM_SMEM>>>(x1h, x1l, wh + 2*WT_ONE, wl + 2*WT_ONE, b1_1,
                                         nullptr, h1h, h1l, D_SZ, 9, 1, H_SZ);
    gemm_mma3<0><<<g2, 256, GEMM_SMEM>>>(h1h, h1l, wh + 3*WT_ONE, wl + 3*WT_ONE, b2_1,
                                         eo, nullptr, nullptr, H_SZ, E_SZ, 0, D_SZ);
    gate_kernel<<<(B_SZ * 8 + 7) / 8, 256>>>(x1, Wg_1, bg_1, sewt, sews, Gp, 8, 1);
    combine_kernel<<<B_SZ, 256>>>(eo, Gp, out, nullptr, nullptr, 8);
}

// round 6
// speedup vs baseline: 2.8148x; 1.0740x over previous
#include <cuda_runtime.h>
#include <cuda_bf16.h>
#include <cstdint>
#include <math.h>

// Problem constants
#define B_SZ 1024
#define D_SZ 512
#define H_SZ 1024
#define T_SZ 8
#define E_SZ 18

// ==================== PTX helpers (plain sm_103-safe: mma.sync / ldmatrix / cp.async) ====
__device__ __forceinline__ uint32_t smem_to_u32(const void* p) {
    uint32_t a;
    asm("{ .reg .u64 t; cvta.to.shared.u64 t, %1; cvt.u32.u64 %0, t; }" : "=r"(a) : "l"(p));
    return a;
}
#define CP_ASYNC16(dst, src) \
    asm volatile("cp.async.cg.shared.global [%0], [%1], 16;" :: "r"(dst), "l"(src))
#define CP_COMMIT() asm volatile("cp.async.commit_group;" ::: "memory")
#define CP_WAIT1()  asm volatile("cp.async.wait_group 1;" ::: "memory")

#define LDSM_X4(r, a) \
    asm volatile("ldmatrix.sync.aligned.m8n8.x4.shared.b16 {%0,%1,%2,%3}, [%4];" \
        : "=r"((r)[0]), "=r"((r)[1]), "=r"((r)[2]), "=r"((r)[3]) : "r"(a))
#define LDSM_X4T(r, a) \
    asm volatile("ldmatrix.sync.aligned.m8n8.x4.trans.shared.b16 {%0,%1,%2,%3}, [%4];" \
        : "=r"((r)[0]), "=r"((r)[1]), "=r"((r)[2]), "=r"((r)[3]) : "r"(a))

#define MMA16816(c, a, b0, b1) \
    asm volatile("mma.sync.aligned.m16n8k16.row.col.f32.bf16.bf16.f32 " \
        "{%0,%1,%2,%3}, {%4,%5,%6,%7}, {%8,%9}, {%0,%1,%2,%3};" \
        : "+f"((c)[0]), "+f"((c)[1]), "+f"((c)[2]), "+f"((c)[3]) \
        : "r"((a)[0]), "r"((a)[1]), "r"((a)[2]), "r"((a)[3]), "r"(b0), "r"(b1))

// ==================== scratch (static device globals) ====================
__device__ __nv_bfloat16 g_xh [B_SZ * 9 * D_SZ];
__device__ __nv_bfloat16 g_xl [B_SZ * 9 * D_SZ];
#define WT_ONE (E_SZ * H_SZ * D_SZ)            // 9,437,184 elems per weight tensor
__device__ __nv_bfloat16 g_wh[4 * WT_ONE];     // (E,K,N) native layout hi: W1_0,W2_0,W1_1,W2_1
__device__ __nv_bfloat16 g_wl[4 * WT_ONE];
__device__ __nv_bfloat16 g_h1h[B_SZ * E_SZ * H_SZ];
__device__ __nv_bfloat16 g_h1l[B_SZ * E_SZ * H_SZ];
__device__ float         g_eo [B_SZ * E_SZ * D_SZ];
__device__ float         g_x1 [B_SZ * 9 * D_SZ];
__device__ __nv_bfloat16 g_x1h[B_SZ * 9 * D_SZ];
__device__ __nv_bfloat16 g_x1l[B_SZ * 9 * D_SZ];
__device__ float         g_G  [B_SZ * 9 * E_SZ];

// ==================== prep: fp32 -> bf16 hi/lo split (elementwise, 2x ILP) ============
__global__ __launch_bounds__(256)
void split_f32(const float* __restrict__ X, __nv_bfloat16* __restrict__ H,
               __nv_bfloat16* __restrict__ L, int n4)
{
    int i0 = (blockIdx.x * blockDim.x + threadIdx.x) * 2;
    #pragma unroll
    for (int u = 0; u < 2; ++u) {
        int i = i0 + u;
        if (i >= n4) return;
        float4 v = ((const float4*)X)[i];
        __nv_bfloat16 h0 = __float2bfloat16(v.x), h1 = __float2bfloat16(v.y);
        __nv_bfloat16 h2 = __float2bfloat16(v.z), h3 = __float2bfloat16(v.w);
        __nv_bfloat162 hp0 = {h0, h1}, hp1 = {h2, h3};
        __nv_bfloat162 lp0 = {__float2bfloat16(v.x - __bfloat162float(h0)),
                              __float2bfloat16(v.y - __bfloat162float(h1))};
        __nv_bfloat162 lp1 = {__float2bfloat16(v.z - __bfloat162float(h2)),
                              __float2bfloat16(v.w - __bfloat162float(h3))};
        ((__nv_bfloat162*)H)[2*i]   = hp0; ((__nv_bfloat162*)H)[2*i+1] = hp1;
        ((__nv_bfloat162*)L)[2*i]   = lp0; ((__nv_bfloat162*)L)[2*i+1] = lp1;
    }
}

// ==================== GEMM: mma.sync bf16 3-term split ====================
// C[m,e,n] (pitch 18*Ntot) = act( sum_k A[(m*a_mul+(e>>a_shift)), k] * W[e, k, n] + bias[e,n] )
// A: k-major rows (hi/lo). W: (E, K, N) native n-major rows (hi/lo), via ldmatrix.trans.
// 128x128 tile, BK=64, 3-stage cp.async pipeline (R4-proven ordering:
// wait -> sync -> load -> compute; ONE __syncthreads per ktile).
// 8 warps (4m x 2n), warp tile 32x64.
#define STAGE_BYTES 65536
#define GEMM_SMEM   (1024 + 3 * STAGE_BYTES)

template<int EPI_BF16>
__global__ __launch_bounds__(256, 1)
void gemm_mma3(const __nv_bfloat16* __restrict__ Ah, const __nv_bfloat16* __restrict__ Al,
               const __nv_bfloat16* __restrict__ Bh, const __nv_bfloat16* __restrict__ Bl,
               const float* __restrict__ bias,
               float* __restrict__ Cf, __nv_bfloat16* __restrict__ Ch,
               __nv_bfloat16* __restrict__ Cl,
               int K, int a_mul, int a_shift, int Ntot)
{
    extern __shared__ char smem[];
    const uint32_t su = smem_to_u32(smem);
    const int tid  = threadIdx.x;
    const int wid  = tid >> 5;
    const int lane = tid & 31;
    const int e  = blockIdx.z;
    const int m0 = blockIdx.y * 128;
    const int n0 = blockIdx.x * 128;
    const int warp_m = wid & 3;     // 4 warps in m
    const int warp_n = wid >> 2;    // 2 warps in n
    const int esel = e >> a_shift;

    // bias -> smem [0..511]
    if (tid < 128)
        ((float*)smem)[tid] = bias[(size_t)e * Ntot + n0 + tid];

    // ---- stage loader (cp.async), BK=64 ----
    // A tile: 128 rows x 64 k  (128B rows, 8 chunks), swizzle ac ^ (row & 7)
    // B tile: 64 k-rows x 128 n (256B rows, 16 chunks), swizzle nc ^ (krow & 7)
    auto load_stage = [&](int s, int k0) {
        uint32_t st = su + 1024 + s * STAGE_BYTES;
        #pragma unroll
        for (int t = 0; t < 4; ++t) {
            int idx = tid + t * 256;
            int arow = idx >> 3, ac = idx & 7;
            size_t aoff = ((size_t)(m0 + arow) * a_mul + esel) * K + k0 + ac * 8;
            uint32_t ad = arow * 128 + ((ac ^ (arow & 7)) << 4);
            CP_ASYNC16(st + ad,         Ah + aoff);
            CP_ASYNC16(st + 16384 + ad, Al + aoff);
            int krow = idx >> 4, nc = idx & 15;
            size_t boff = ((size_t)e * K + k0 + krow) * Ntot + n0 + nc * 8;
            uint32_t bd = krow * 256 + ((nc ^ (krow & 7)) << 4);
            CP_ASYNC16(st + 32768 + bd, Bh + boff);
            CP_ASYNC16(st + 49152 + bd, Bl + boff);
        }
        CP_COMMIT();
    };

    float c[2][8][4];
    #pragma unroll
    for (int i = 0; i < 2; i++)
        #pragma unroll
        for (int j = 0; j < 8; j++)
            #pragma unroll
            for (int q = 0; q < 4; q++) c[i][j][q] = 0.f;

    const int nk = K >> 6;   // 8 (K=512) or 16 (K=1024)
    load_stage(0, 0);
    load_stage(1, 64);

    // precomputed ldmatrix address components
    const int a_rl   = (lane & 7) + ((lane >> 3) & 1) * 8;  // row within 16-row frag
    const int a_kc_h = lane >> 4;                           // 0/1: k chunk half
    const int b_kl   = (lane & 7) + ((lane >> 3) & 1) * 8;  // k row within 16
    const int b_nc_h = lane >> 4;                           // 0/1: n chunk half

    int s = 0;
    for (int cIt = 0; cIt < nk; ++cIt) {
        CP_WAIT1();            // this thread's stage-cIt copies done (pending <= 1 group)
        __syncthreads();       // ALL threads' stage-cIt copies visible; prior compute drained
        if (cIt + 2 < nk) {
            int sn = s + 2;
            if (sn >= 3) sn -= 3;
            load_stage(sn, (cIt + 2) << 6);
        } else {
            CP_COMMIT();       // keep group accounting aligned for CP_WAIT1
        }

        uint32_t st = su + 1024 + s * STAGE_BYTES;
        #pragma unroll
        for (int ks = 0; ks < 4; ++ks) {
            uint32_t ah[2][4], al[2][4];
            #pragma unroll
            for (int mi = 0; mi < 2; ++mi) {
                int row = warp_m * 32 + mi * 16 + a_rl;
                int kc  = ks * 2 + a_kc_h;
                uint32_t ad = st + row * 128 + ((kc ^ (row & 7)) << 4);
                LDSM_X4(ah[mi], ad);
                LDSM_X4(al[mi], ad + 16384);
            }
            uint32_t bh[4][4], bl[4][4];
            #pragma unroll
            for (int ni = 0; ni < 4; ++ni) {
                int krow = ks * 16 + b_kl;
                int nc   = warp_n * 8 + ni * 2 + b_nc_h;
                uint32_t bd = st + 32768 + krow * 256 + ((nc ^ (krow & 7)) << 4);
                LDSM_X4T(bh[ni], bd);
                LDSM_X4T(bl[ni], bd + 16384);
            }
            #pragma unroll
            for (int mi = 0; mi < 2; ++mi)
                #pragma unroll
                for (int ni = 0; ni < 4; ++ni)
                    #pragma unroll
                    for (int h = 0; h < 2; ++h) {
                        float* cc = c[mi][ni * 2 + h];
                        uint32_t bh0 = bh[ni][h * 2], bh1 = bh[ni][h * 2 + 1];
                        uint32_t bl0 = bl[ni][h * 2], bl1 = bl[ni][h * 2 + 1];
                        MMA16816(cc, ah[mi], bh0, bh1);
                        MMA16816(cc, ah[mi], bl0, bl1);
                        MMA16816(cc, al[mi], bh0, bh1);
                    }
        }
        s = (s == 2) ? 0 : s + 1;
    }

    // ---- epilogue ----
    const float* bs = (const float*)smem;
    #pragma unroll
    for (int mi = 0; mi < 2; ++mi) {
        int r0 = m0 + warp_m * 32 + mi * 16 + (lane >> 2);
        #pragma unroll
        for (int h2 = 0; h2 < 2; ++h2) {
            int row = r0 + h2 * 8;
            size_t cbase = ((size_t)row * E_SZ + e) * Ntot;
            #pragma unroll
            for (int nj = 0; nj < 8; ++nj) {
                int col = warp_n * 64 + nj * 8 + (lane & 3) * 2;   // relative to n0
                float v0 = c[mi][nj][h2 * 2]     + bs[col];
                float v1 = c[mi][nj][h2 * 2 + 1] + bs[col + 1];
                if (EPI_BF16) {
                    v0 = fmaxf(v0, 0.f); v1 = fmaxf(v1, 0.f);
                    __nv_bfloat16 hh0 = __float2bfloat16(v0);
                    __nv_bfloat16 hh1 = __float2bfloat16(v1);
                    __nv_bfloat162 hp = {hh0, hh1};
                    __nv_bfloat162 lp = {__float2bfloat16(v0 - __bfloat162float(hh0)),
                                         __float2bfloat16(v1 - __bfloat162float(hh1))};
                    *(uint32_t*)(Ch + cbase + n0 + col) = *(uint32_t*)&hp;
                    *(uint32_t*)(Cl + cbase + n0 + col) = *(uint32_t*)&lp;
                } else {
                    *(float2*)(Cf + cbase + n0 + col) = make_float2(v0, v1);
                }
            }
        }
    }
}

// ==================== gate: softmax(x[:, :M] @ Wg + bg) + add ====================
__global__ __launch_bounds__(256)
void gate_kernel(const float* __restrict__ x,
                 const float* __restrict__ Wg,
                 const float* __restrict__ bg,
                 const float* __restrict__ sew_task,
                 const float* __restrict__ sew_shared,
                 float* __restrict__ G,
                 int M, int layer)
{
    __shared__ float xs[8][D_SZ];
    const int wl   = threadIdx.x >> 5;
    const int lane = threadIdx.x & 31;
    const int wg   = blockIdx.x * 8 + wl;
    if (wg >= B_SZ * M) return;
    const int b = wg / M;
    const int m = wg - b * M;

    const float* xr = x + ((size_t)b * 9 + m) * D_SZ;
    for (int k = lane; k < D_SZ; k += 32) xs[wl][k] = xr[k];
    __syncwarp();

    float acc = 0.f;
    if (lane < E_SZ) {
        const float* w = Wg + (size_t)m * D_SZ * E_SZ + lane;
        #pragma unroll 4
        for (int k = 0; k < D_SZ; k++)
            acc += xs[wl][k] * w[(size_t)k * E_SZ];
        acc += bg[m * E_SZ + lane];
    }
    float v = (lane < E_SZ) ? acc : -3.4e38f;
    float mx = v;
    #pragma unroll
    for (int o = 16; o > 0; o >>= 1)
        mx = fmaxf(mx, __shfl_xor_sync(0xffffffffu, mx, o));
    float ex = (lane < E_SZ) ? expf(v - mx) : 0.f;
    float s = ex;
    #pragma unroll
    for (int o = 16; o > 0; o >>= 1)
        s += __shfl_xor_sync(0xffffffffu, s, o);

    if (lane < E_SZ) {
        float g = ex / s;
        float addv = 0.f;
        if (layer == 0) {
            if (m < T_SZ && (lane >> 1) == m) addv = sew_task[m * 4 + (lane & 1)];
            if (m == T_SZ && lane >= 16)      addv = sew_shared[lane - 16];
        } else {
            if ((lane >> 1) == m)             addv = sew_task[m * 4 + 2 + (lane & 1)];
        }
        G[((size_t)b * M + m) * E_SZ + lane] = g + addv;
    }
}

// ==================== combine: out[b,m,:] = sum_e G[b,m,e] * EO[b,e,:] ====================
__global__ __launch_bounds__(256)
void combine_kernel(const float* __restrict__ EO,
                    const float* __restrict__ G,
                    float* __restrict__ OUT,
                    __nv_bfloat16* __restrict__ OH,
                    __nv_bfloat16* __restrict__ OL,
                    int M)
{
    __shared__ float gs[9 * E_SZ];
    const int b   = blockIdx.x;
    const int tid = threadIdx.x;
    if (tid < M * E_SZ) gs[tid] = G[(size_t)b * M * E_SZ + tid];
    __syncthreads();

    const float* eo = EO + (size_t)b * E_SZ * D_SZ;
    for (int d = tid; d < D_SZ; d += 256) {
        float ev[E_SZ];
        #pragma unroll
        for (int e2 = 0; e2 < E_SZ; e2++)
            ev[e2] = eo[(size_t)e2 * D_SZ + d];
        for (int m = 0; m < M; m++) {
            float s = 0.f;
            #pragma unroll
            for (int e2 = 0; e2 < E_SZ; e2++)
                s += gs[m * E_SZ + e2] * ev[e2];
            if (OH) {
                size_t o = ((size_t)b * 9 + m) * D_SZ + d;   // pitch-9 for layer chaining
                OUT[o] = s;
                __nv_bfloat16 h = __float2bfloat16(s);
                OH[o] = h;
                OL[o] = __float2bfloat16(s - __bfloat162float(h));
            } else {
                OUT[((size_t)b * M + m) * D_SZ + d] = s;     // final (B,8,D) contiguous
            }
        }
    }
}

// ==================== launcher ====================
extern "C" void kernel_launch(void* const* d_in, const int* in_sizes, int n_in,
                              void* d_out, int out_size)
{
    const float* x_in  = (const float*)d_in[0];
    const float* W1_0  = (const float*)d_in[1];
    const float* b1_0  = (const float*)d_in[2];
    const float* W2_0  = (const float*)d_in[3];
    const float* b2_0  = (const float*)d_in[4];
    const float* Wg_0  = (const float*)d_in[5];
    const float* bg_0  = (const float*)d_in[6];
    const float* W1_1  = (const float*)d_in[7];
    const float* b1_1  = (const float*)d_in[8];
    const float* W2_1  = (const float*)d_in[9];
    const float* b2_1  = (const float*)d_in[10];
    const float* Wg_1  = (const float*)d_in[11];
    const float* bg_1  = (const float*)d_in[12];
    const float* sewt  = (const float*)d_in[13];
    const float* sews  = (const float*)d_in[14];
    float* out = (float*)d_out;

    __nv_bfloat16 *xh, *xl, *wh, *wl, *h1h, *h1l, *x1h, *x1l;
    float *eo, *x1, *Gp;
    cudaGetSymbolAddress((void**)&xh,  g_xh);
    cudaGetSymbolAddress((void**)&xl,  g_xl);
    cudaGetSymbolAddress((void**)&wh,  g_wh);
    cudaGetSymbolAddress((void**)&wl,  g_wl);
    cudaGetSymbolAddress((void**)&h1h, g_h1h);
    cudaGetSymbolAddress((void**)&h1l, g_h1l);
    cudaGetSymbolAddress((void**)&eo,  g_eo);
    cudaGetSymbolAddress((void**)&x1,  g_x1);
    cudaGetSymbolAddress((void**)&x1h, g_x1h);
    cudaGetSymbolAddress((void**)&x1l, g_x1l);
    cudaGetSymbolAddress((void**)&Gp,  g_G);

    cudaFuncSetAttribute(gemm_mma3<1>, cudaFuncAttributeMaxDynamicSharedMemorySize, GEMM_SMEM);
    cudaFuncSetAttribute(gemm_mma3<0>, cudaFuncAttributeMaxDynamicSharedMemorySize, GEMM_SMEM);

    // ---- prep: hi/lo splits (weights stay in native (E,K,N) layout) ----
    int n4x = B_SZ * 9 * D_SZ / 4;
    split_f32<<<(n4x/2 + 255) / 256, 256>>>(x_in, xh, xl, n4x);
    int n4w = WT_ONE / 4;
    int gw = (n4w/2 + 255) / 256;
    split_f32<<<gw, 256>>>(W1_0, wh + 0*WT_ONE, wl + 0*WT_ONE, n4w);
    split_f32<<<gw, 256>>>(W2_0, wh + 1*WT_ONE, wl + 1*WT_ONE, n4w);
    split_f32<<<gw, 256>>>(W1_1, wh + 2*WT_ONE, wl + 2*WT_ONE, n4w);
    split_f32<<<gw, 256>>>(W2_1, wh + 3*WT_ONE, wl + 3*WT_ONE, n4w);

    dim3 g1(H_SZ / 128, B_SZ / 128, E_SZ);   // (8, 8, 18)
    dim3 g2(D_SZ / 128, B_SZ / 128, E_SZ);   // (4, 8, 18)

    // ---- layer 0 ----
    gemm_mma3<1><<<g1, 256, GEMM_SMEM>>>(xh, xl, wh + 0*WT_ONE, wl + 0*WT_ONE, b1_0,
                                         nullptr, h1h, h1l, D_SZ, 9, 1, H_SZ);
    gemm_mma3<0><<<g2, 256, GEMM_SMEM>>>(h1h, h1l, wh + 1*WT_ONE, wl + 1*WT_ONE, b2_0,
                                         eo, nullptr, nullptr, H_SZ, E_SZ, 0, D_SZ);
    gate_kernel<<<(B_SZ * 9 + 7) / 8, 256>>>(x_in, Wg_0, bg_0, sewt, sews, Gp, 9, 0);
    combine_kernel<<<B_SZ, 256>>>(eo, Gp, x1, x1h, x1l, 9);

    // ---- layer 1 ----
    gemm_mma3<1><<<g1, 256, GEMM_SMEM>>>(x1h, x1l, wh + 2*WT_ONE, wl + 2*WT_ONE, b1_1,
                                         nullptr, h1h, h1l, D_SZ, 9, 1, H_SZ);
    gemm_mma3<0><<<g2, 256, GEMM_SMEM>>>(h1h, h1l, wh + 3*WT_ONE, wl + 3*WT_ONE, b2_1,
                                         eo, nullptr, nullptr, H_SZ, E_SZ, 0, D_SZ);
    gate_kernel<<<(B_SZ * 8 + 7) / 8, 256>>>(x1, Wg_1, bg_1, sewt, sews, Gp, 8, 1);
    combine_kernel<<<B_SZ, 256>>>(eo, Gp, out, nullptr, nullptr, 8);
}

// round 7
// speedup vs baseline: 3.5957x; 1.2774x over previous
#include <cuda_runtime.h>
#include <cuda_fp16.h>
#include <cstdint>
#include <math.h>

// Problem constants
#define B_SZ 1024
#define D_SZ 512
#define H_SZ 1024
#define T_SZ 8
#define E_SZ 18

// ==================== PTX helpers ====================
__device__ __forceinline__ uint32_t smem_to_u32(const void* p) {
    uint32_t a;
    asm("{ .reg .u64 t; cvta.to.shared.u64 t, %1; cvt.u32.u64 %0, t; }" : "=r"(a) : "l"(p));
    return a;
}
#define CP_ASYNC16(dst, src) \
    asm volatile("cp.async.cg.shared.global [%0], [%1], 16;" :: "r"(dst), "l"(src))
#define CP_COMMIT() asm volatile("cp.async.commit_group;" ::: "memory")
#define CP_WAIT1()  asm volatile("cp.async.wait_group 1;" ::: "memory")

#define LDSM_X4(r, a) \
    asm volatile("ldmatrix.sync.aligned.m8n8.x4.shared.b16 {%0,%1,%2,%3}, [%4];" \
        : "=r"((r)[0]), "=r"((r)[1]), "=r"((r)[2]), "=r"((r)[3]) : "r"(a))
#define LDSM_X4T(r, a) \
    asm volatile("ldmatrix.sync.aligned.m8n8.x4.trans.shared.b16 {%0,%1,%2,%3}, [%4];" \
        : "=r"((r)[0]), "=r"((r)[1]), "=r"((r)[2]), "=r"((r)[3]) : "r"(a))

// f16 mma, fp32 accumulate
#define MMA16816H(c, a, b0, b1) \
    asm volatile("mma.sync.aligned.m16n8k16.row.col.f32.f16.f16.f32 " \
        "{%0,%1,%2,%3}, {%4,%5,%6,%7}, {%8,%9}, {%0,%1,%2,%3};" \
        : "+f"((c)[0]), "+f"((c)[1]), "+f"((c)[2]), "+f"((c)[3]) \
        : "r"((a)[0]), "r"((a)[1]), "r"((a)[2]), "r"((a)[3]), "r"(b0), "r"(b1))

// ==================== scratch (static device globals) ====================
__device__ __half g_xh [B_SZ * 9 * D_SZ];
__device__ __half g_xl [B_SZ * 9 * D_SZ];
#define WT_ONE (E_SZ * H_SZ * D_SZ)            // 9,437,184 elems per weight tensor
__device__ __half g_w[4 * WT_ONE];             // (E,K,N) native layout fp16: W1_0,W2_0,W1_1,W2_1
__device__ __half g_h1h[B_SZ * E_SZ * H_SZ];
__device__ __half g_h1l[B_SZ * E_SZ * H_SZ];
__device__ float  g_eo [B_SZ * E_SZ * D_SZ];
__device__ float  g_x1 [B_SZ * 9 * D_SZ];
__device__ __half g_x1h[B_SZ * 9 * D_SZ];
__device__ __half g_x1l[B_SZ * 9 * D_SZ];
__device__ float  g_G  [B_SZ * 9 * E_SZ];

// ==================== prep: fp32 -> fp16 hi/lo split (activations) ====================
__global__ __launch_bounds__(256)
void split_f32h(const float* __restrict__ X, __half* __restrict__ H,
                __half* __restrict__ L, int n4)
{
    int i0 = (blockIdx.x * blockDim.x + threadIdx.x) * 2;
    #pragma unroll
    for (int u = 0; u < 2; ++u) {
        int i = i0 + u;
        if (i >= n4) return;
        float4 v = ((const float4*)X)[i];
        __half h0 = __float2half_rn(v.x), h1 = __float2half_rn(v.y);
        __half h2 = __float2half_rn(v.z), h3 = __float2half_rn(v.w);
        __half2 hp0 = {h0, h1}, hp1 = {h2, h3};
        __half2 lp0 = {__float2half_rn(v.x - __half2float(h0)),
                       __float2half_rn(v.y - __half2float(h1))};
        __half2 lp1 = {__float2half_rn(v.z - __half2float(h2)),
                       __float2half_rn(v.w - __half2float(h3))};
        ((__half2*)H)[2*i]   = hp0; ((__half2*)H)[2*i+1] = hp1;
        ((__half2*)L)[2*i]   = lp0; ((__half2*)L)[2*i+1] = lp1;
    }
}

// ==================== prep: fp32 -> fp16 convert (weights, single term) ====================
__global__ __launch_bounds__(256)
void conv_f32h(const float* __restrict__ X, __half* __restrict__ H, int n4)
{
    int i0 = (blockIdx.x * blockDim.x + threadIdx.x) * 2;
    #pragma unroll
    for (int u = 0; u < 2; ++u) {
        int i = i0 + u;
        if (i >= n4) return;
        float4 v = ((const float4*)X)[i];
        __half2 hp0 = {__float2half_rn(v.x), __float2half_rn(v.y)};
        __half2 hp1 = {__float2half_rn(v.z), __float2half_rn(v.w)};
        ((__half2*)H)[2*i]   = hp0;
        ((__half2*)H)[2*i+1] = hp1;
    }
}

// ==================== GEMM: mma.sync fp16 2-term (A split hi/lo, W single) ============
// C[m,e,n] (pitch 18*Ntot) = act( sum_k A[(m*a_mul+(e>>a_shift)), k] * W[e, k, n] + bias[e,n] )
// A: k-major rows (hi/lo fp16). W: (E, K, N) native n-major rows fp16, via ldmatrix.trans.
// 128x128 tile, BK=64, 3-stage cp.async (wait -> sync -> load -> compute, one sync/ktile).
// 8 warps (4m x 2n), warp tile 32x64.
#define STAGE_BYTES 49152
#define GEMM_SMEM   (1024 + 3 * STAGE_BYTES)

template<int EPI_F16>
__global__ __launch_bounds__(256, 1)
void gemm_mma2(const __half* __restrict__ Ah, const __half* __restrict__ Al,
               const __half* __restrict__ Bw,
               const float* __restrict__ bias,
               float* __restrict__ Cf, __half* __restrict__ Ch, __half* __restrict__ Cl,
               int K, int a_mul, int a_shift, int Ntot)
{
    extern __shared__ char smem[];
    const uint32_t su = smem_to_u32(smem);
    const int tid  = threadIdx.x;
    const int wid  = tid >> 5;
    const int lane = tid & 31;
    const int e  = blockIdx.z;
    const int m0 = blockIdx.y * 128;
    const int n0 = blockIdx.x * 128;
    const int warp_m = wid & 3;     // 4 warps in m
    const int warp_n = wid >> 2;    // 2 warps in n
    const int esel = e >> a_shift;

    if (tid < 128)
        ((float*)smem)[tid] = bias[(size_t)e * Ntot + n0 + tid];

    // ---- stage loader (cp.async), BK=64 ----
    // A tiles (hi @0, lo @16384): 128 rows x 64 k (128B rows, 8 chunks), swizzle ac ^ (row&7)
    // B tile  (@32768):           64 k-rows x 128 n (256B rows, 16 chunks), swizzle nc ^ (krow&7)
    auto load_stage = [&](int s, int k0) {
        uint32_t st = su + 1024 + s * STAGE_BYTES;
        #pragma unroll
        for (int t = 0; t < 4; ++t) {
            int idx = tid + t * 256;
            int arow = idx >> 3, ac = idx & 7;
            size_t aoff = ((size_t)(m0 + arow) * a_mul + esel) * K + k0 + ac * 8;
            uint32_t ad = arow * 128 + ((ac ^ (arow & 7)) << 4);
            CP_ASYNC16(st + ad,         Ah + aoff);
            CP_ASYNC16(st + 16384 + ad, Al + aoff);
            int krow = idx >> 4, nc = idx & 15;
            size_t boff = ((size_t)e * K + k0 + krow) * Ntot + n0 + nc * 8;
            uint32_t bd = krow * 256 + ((nc ^ (krow & 7)) << 4);
            CP_ASYNC16(st + 32768 + bd, Bw + boff);
        }
        CP_COMMIT();
    };

    float c[2][8][4];
    #pragma unroll
    for (int i = 0; i < 2; i++)
        #pragma unroll
        for (int j = 0; j < 8; j++)
            #pragma unroll
            for (int q = 0; q < 4; q++) c[i][j][q] = 0.f;

    const int nk = K >> 6;
    load_stage(0, 0);
    load_stage(1, 64);

    const int a_rl   = (lane & 7) + ((lane >> 3) & 1) * 8;
    const int a_kc_h = lane >> 4;
    const int b_kl   = (lane & 7) + ((lane >> 3) & 1) * 8;
    const int b_nc_h = lane >> 4;

    int s = 0;
    for (int cIt = 0; cIt < nk; ++cIt) {
        CP_WAIT1();            // this thread's stage-cIt copies done
        __syncthreads();       // ALL threads' copies visible; prior compute drained
        if (cIt + 2 < nk) {
            int sn = s + 2;
            if (sn >= 3) sn -= 3;
            load_stage(sn, (cIt + 2) << 6);
        } else {
            CP_COMMIT();
        }

        uint32_t st = su + 1024 + s * STAGE_BYTES;
        #pragma unroll
        for (int ks = 0; ks < 4; ++ks) {
            uint32_t ah[2][4], al[2][4];
            #pragma unroll
            for (int mi = 0; mi < 2; ++mi) {
                int row = warp_m * 32 + mi * 16 + a_rl;
                int kc  = ks * 2 + a_kc_h;
                uint32_t ad = st + row * 128 + ((kc ^ (row & 7)) << 4);
                LDSM_X4(ah[mi], ad);
                LDSM_X4(al[mi], ad + 16384);
            }
            uint32_t bw[4][4];
            #pragma unroll
            for (int ni = 0; ni < 4; ++ni) {
                int krow = ks * 16 + b_kl;
                int nc   = warp_n * 8 + ni * 2 + b_nc_h;
                uint32_t bd = st + 32768 + krow * 256 + ((nc ^ (krow & 7)) << 4);
                LDSM_X4T(bw[ni], bd);
            }
            #pragma unroll
            for (int mi = 0; mi < 2; ++mi)
                #pragma unroll
                for (int ni = 0; ni < 4; ++ni)
                    #pragma unroll
                    for (int h = 0; h < 2; ++h) {
                        float* cc = c[mi][ni * 2 + h];
                        uint32_t b0 = bw[ni][h * 2], b1 = bw[ni][h * 2 + 1];
                        MMA16816H(cc, ah[mi], b0, b1);
                        MMA16816H(cc, al[mi], b0, b1);
                    }
        }
        s = (s == 2) ? 0 : s + 1;
    }

    // ---- epilogue ----
    const float* bs = (const float*)smem;
    #pragma unroll
    for (int mi = 0; mi < 2; ++mi) {
        int r0 = m0 + warp_m * 32 + mi * 16 + (lane >> 2);
        #pragma unroll
        for (int h2 = 0; h2 < 2; ++h2) {
            int row = r0 + h2 * 8;
            size_t cbase = ((size_t)row * E_SZ + e) * Ntot;
            #pragma unroll
            for (int nj = 0; nj < 8; ++nj) {
                int col = warp_n * 64 + nj * 8 + (lane & 3) * 2;
                float v0 = c[mi][nj][h2 * 2]     + bs[col];
                float v1 = c[mi][nj][h2 * 2 + 1] + bs[col + 1];
                if (EPI_F16) {
                    v0 = fmaxf(v0, 0.f); v1 = fmaxf(v1, 0.f);
                    __half hh0 = __float2half_rn(v0);
                    __half hh1 = __float2half_rn(v1);
                    __half2 hp = {hh0, hh1};
                    __half2 lp = {__float2half_rn(v0 - __half2float(hh0)),
                                  __float2half_rn(v1 - __half2float(hh1))};
                    *(uint32_t*)(Ch + cbase + n0 + col) = *(uint32_t*)&hp;
                    *(uint32_t*)(Cl + cbase + n0 + col) = *(uint32_t*)&lp;
                } else {
                    *(float2*)(Cf + cbase + n0 + col) = make_float2(v0, v1);
                }
            }
        }
    }
}

// ==================== gate: softmax(x[:, :M] @ Wg + bg) + add ====================
__global__ __launch_bounds__(256)
void gate_kernel(const float* __restrict__ x,
                 const float* __restrict__ Wg,
                 const float* __restrict__ bg,
                 const float* __restrict__ sew_task,
                 const float* __restrict__ sew_shared,
                 float* __restrict__ G,
                 int M, int layer)
{
    __shared__ float xs[8][D_SZ];
    const int wl   = threadIdx.x >> 5;
    const int lane = threadIdx.x & 31;
    const int wg   = blockIdx.x * 8 + wl;
    if (wg >= B_SZ * M) return;
    const int b = wg / M;
    const int m = wg - b * M;

    const float* xr = x + ((size_t)b * 9 + m) * D_SZ;
    for (int k = lane; k < D_SZ; k += 32) xs[wl][k] = xr[k];
    __syncwarp();

    float acc = 0.f;
    if (lane < E_SZ) {
        const float* w = Wg + (size_t)m * D_SZ * E_SZ + lane;
        #pragma unroll 4
        for (int k = 0; k < D_SZ; k++)
            acc += xs[wl][k] * w[(size_t)k * E_SZ];
        acc += bg[m * E_SZ + lane];
    }
    float v = (lane < E_SZ) ? acc : -3.4e38f;
    float mx = v;
    #pragma unroll
    for (int o = 16; o > 0; o >>= 1)
        mx = fmaxf(mx, __shfl_xor_sync(0xffffffffu, mx, o));
    float ex = (lane < E_SZ) ? expf(v - mx) : 0.f;
    float s = ex;
    #pragma unroll
    for (int o = 16; o > 0; o >>= 1)
        s += __shfl_xor_sync(0xffffffffu, s, o);

    if (lane < E_SZ) {
        float g = ex / s;
        float addv = 0.f;
        if (layer == 0) {
            if (m < T_SZ && (lane >> 1) == m) addv = sew_task[m * 4 + (lane & 1)];
            if (m == T_SZ && lane >= 16)      addv = sew_shared[lane - 16];
        } else {
            if ((lane >> 1) == m)             addv = sew_task[m * 4 + 2 + (lane & 1)];
        }
        G[((size_t)b * M + m) * E_SZ + lane] = g + addv;
    }
}

// ==================== combine: out[b,m,:] = sum_e G[b,m,e] * EO[b,e,:] ====================
__global__ __launch_bounds__(256)
void combine_kernel(const float* __restrict__ EO,
                    const float* __restrict__ G,
                    float* __restrict__ OUT,
                    __half* __restrict__ OH,
                    __half* __restrict__ OL,
                    int M)
{
    __shared__ float gs[9 * E_SZ];
    const int b   = blockIdx.x;
    const int tid = threadIdx.x;
    if (tid < M * E_SZ) gs[tid] = G[(size_t)b * M * E_SZ + tid];
    __syncthreads();

    const float* eo = EO + (size_t)b * E_SZ * D_SZ;
    for (int d = tid; d < D_SZ; d += 256) {
        float ev[E_SZ];
        #pragma unroll
        for (int e2 = 0; e2 < E_SZ; e2++)
            ev[e2] = eo[(size_t)e2 * D_SZ + d];
        for (int m = 0; m < M; m++) {
            float s = 0.f;
            #pragma unroll
            for (int e2 = 0; e2 < E_SZ; e2++)
                s += gs[m * E_SZ + e2] * ev[e2];
            if (OH) {
                size_t o = ((size_t)b * 9 + m) * D_SZ + d;   // pitch-9 for layer chaining
                OUT[o] = s;
                __half h = __float2half_rn(s);
                OH[o] = h;
                OL[o] = __float2half_rn(s - __half2float(h));
            } else {
                OUT[((size_t)b * M + m) * D_SZ + d] = s;     // final (B,8,D) contiguous
            }
        }
    }
}

// ==================== launcher ====================
extern "C" void kernel_launch(void* const* d_in, const int* in_sizes, int n_in,
                              void* d_out, int out_size)
{
    const float* x_in  = (const float*)d_in[0];
    const float* W1_0  = (const float*)d_in[1];
    const float* b1_0  = (const float*)d_in[2];
    const float* W2_0  = (const float*)d_in[3];
    const float* b2_0  = (const float*)d_in[4];
    const float* Wg_0  = (const float*)d_in[5];
    const float* bg_0  = (const float*)d_in[6];
    const float* W1_1  = (const float*)d_in[7];
    const float* b1_1  = (const float*)d_in[8];
    const float* W2_1  = (const float*)d_in[9];
    const float* b2_1  = (const float*)d_in[10];
    const float* Wg_1  = (const float*)d_in[11];
    const float* bg_1  = (const float*)d_in[12];
    const float* sewt  = (const float*)d_in[13];
    const float* sews  = (const float*)d_in[14];
    float* out = (float*)d_out;

    __half *xh, *xl, *w, *h1h, *h1l, *x1h, *x1l;
    float *eo, *x1, *Gp;
    cudaGetSymbolAddress((void**)&xh,  g_xh);
    cudaGetSymbolAddress((void**)&xl,  g_xl);
    cudaGetSymbolAddress((void**)&w,   g_w);
    cudaGetSymbolAddress((void**)&h1h, g_h1h);
    cudaGetSymbolAddress((void**)&h1l, g_h1l);
    cudaGetSymbolAddress((void**)&eo,  g_eo);
    cudaGetSymbolAddress((void**)&x1,  g_x1);
    cudaGetSymbolAddress((void**)&x1h, g_x1h);
    cudaGetSymbolAddress((void**)&x1l, g_x1l);
    cudaGetSymbolAddress((void**)&Gp,  g_G);

    cudaFuncSetAttribute(gemm_mma2<1>, cudaFuncAttributeMaxDynamicSharedMemorySize, GEMM_SMEM);
    cudaFuncSetAttribute(gemm_mma2<0>, cudaFuncAttributeMaxDynamicSharedMemorySize, GEMM_SMEM);

    // ---- prep ----
    int n4x = B_SZ * 9 * D_SZ / 4;
    split_f32h<<<(n4x/2 + 255) / 256, 256>>>(x_in, xh, xl, n4x);
    int n4w = WT_ONE / 4;
    int gw = (n4w/2 + 255) / 256;
    conv_f32h<<<gw, 256>>>(W1_0, w + 0*WT_ONE, n4w);
    conv_f32h<<<gw, 256>>>(W2_0, w + 1*WT_ONE, n4w);
    conv_f32h<<<gw, 256>>>(W1_1, w + 2*WT_ONE, n4w);
    conv_f32h<<<gw, 256>>>(W2_1, w + 3*WT_ONE, n4w);

    dim3 g1(H_SZ / 128, B_SZ / 128, E_SZ);   // (8, 8, 18)
    dim3 g2(D_SZ / 128, B_SZ / 128, E_SZ);   // (4, 8, 18)

    // ---- layer 0 ----
    gemm_mma2<1><<<g1, 256, GEMM_SMEM>>>(xh, xl, w + 0*WT_ONE, b1_0,
                                         nullptr, h1h, h1l, D_SZ, 9, 1, H_SZ);
    gemm_mma2<0><<<g2, 256, GEMM_SMEM>>>(h1h, h1l, w + 1*WT_ONE, b2_0,
                                         eo, nullptr, nullptr, H_SZ, E_SZ, 0, D_SZ);
    gate_kernel<<<(B_SZ * 9 + 7) / 8, 256>>>(x_in, Wg_0, bg_0, sewt, sews, Gp, 9, 0);
    combine_kernel<<<B_SZ, 256>>>(eo, Gp, x1, x1h, x1l, 9);

    // ---- layer 1 ----
    gemm_mma2<1><<<g1, 256, GEMM_SMEM>>>(x1h, x1l, w + 2*WT_ONE, b1_1,
                                         nullptr, h1h, h1l, D_SZ, 9, 1, H_SZ);
    gemm_mma2<0><<<g2, 256, GEMM_SMEM>>>(h1h, h1l, w + 3*WT_ONE, b2_1,
                                         eo, nullptr, nullptr, H_SZ, E_SZ, 0, D_SZ);
    gate_kernel<<<(B_SZ * 8 + 7) / 8, 256>>>(x1, Wg_1, bg_1, sewt, sews, Gp, 8, 1);
    combine_kernel<<<B_SZ, 256>>>(eo, Gp, out, nullptr, nullptr, 8);
}

// round 8
// speedup vs baseline: 5.4551x; 1.5171x over previous
#include <cuda_runtime.h>
#include <cuda_fp16.h>
#include <cstdint>
#include <math.h>

// Problem constants
#define B_SZ 1024
#define D_SZ 512
#define H_SZ 1024
#define T_SZ 8
#define E_SZ 18

// ==================== PTX helpers ====================
__device__ __forceinline__ uint32_t smem_to_u32(const void* p) {
    uint32_t a;
    asm("{ .reg .u64 t; cvta.to.shared.u64 t, %1; cvt.u32.u64 %0, t; }" : "=r"(a) : "l"(p));
    return a;
}
#define CP_ASYNC16(dst, src) \
    asm volatile("cp.async.cg.shared.global [%0], [%1], 16;" :: "r"(dst), "l"(src))
#define CP_COMMIT() asm volatile("cp.async.commit_group;" ::: "memory")
#define CP_WAIT1()  asm volatile("cp.async.wait_group 1;" ::: "memory")

#define LDSM_X4(r, a) \
    asm volatile("ldmatrix.sync.aligned.m8n8.x4.shared.b16 {%0,%1,%2,%3}, [%4];" \
        : "=r"((r)[0]), "=r"((r)[1]), "=r"((r)[2]), "=r"((r)[3]) : "r"(a))
#define LDSM_X4T(r, a) \
    asm volatile("ldmatrix.sync.aligned.m8n8.x4.trans.shared.b16 {%0,%1,%2,%3}, [%4];" \
        : "=r"((r)[0]), "=r"((r)[1]), "=r"((r)[2]), "=r"((r)[3]) : "r"(a))

// f16 mma, fp32 accumulate
#define MMA16816H(c, a, b0, b1) \
    asm volatile("mma.sync.aligned.m16n8k16.row.col.f32.f16.f16.f32 " \
        "{%0,%1,%2,%3}, {%4,%5,%6,%7}, {%8,%9}, {%0,%1,%2,%3};" \
        : "+f"((c)[0]), "+f"((c)[1]), "+f"((c)[2]), "+f"((c)[3]) \
        : "r"((a)[0]), "r"((a)[1]), "r"((a)[2]), "r"((a)[3]), "r"(b0), "r"(b1))

// ==================== scratch (static device globals) ====================
__device__ __half g_xh [B_SZ * 9 * D_SZ];
#define WT_ONE (E_SZ * H_SZ * D_SZ)            // 9,437,184 elems per weight tensor
__device__ __half g_w[4 * WT_ONE];             // (E,K,N) native layout fp16
__device__ __half g_h1 [B_SZ * E_SZ * H_SZ];
__device__ float  g_eo [B_SZ * E_SZ * D_SZ];
__device__ float  g_x1 [B_SZ * 9 * D_SZ];
__device__ __half g_x1h[B_SZ * 9 * D_SZ];
__device__ float  g_G  [B_SZ * 9 * E_SZ];

// ==================== prep: fp32 -> fp16 convert ====================
__global__ __launch_bounds__(256)
void conv_f32h(const float* __restrict__ X, __half* __restrict__ H, int n4)
{
    int i0 = (blockIdx.x * blockDim.x + threadIdx.x) * 2;
    #pragma unroll
    for (int u = 0; u < 2; ++u) {
        int i = i0 + u;
        if (i >= n4) return;
        float4 v = ((const float4*)X)[i];
        __half2 hp0 = {__float2half_rn(v.x), __float2half_rn(v.y)};
        __half2 hp1 = {__float2half_rn(v.z), __float2half_rn(v.w)};
        ((__half2*)H)[2*i]   = hp0;
        ((__half2*)H)[2*i+1] = hp1;
    }
}

// ==================== GEMM: mma.sync fp16 single-term ====================
// C[m,e,n] (pitch 18*Ntot) = act( sum_k A[(m*a_mul+(e>>a_shift)), k] * W[e, k, n] + bias[e,n] )
// A: k-major fp16 rows. W: (E, K, N) native n-major fp16 rows, via ldmatrix.trans.
// 128x128 tile, BK=64, 3-stage cp.async (wait -> sync -> load -> compute, one sync/ktile).
// 8 warps (4m x 2n), warp tile 32x64, 2 CTAs per SM.
#define STAGE_BYTES 32768
#define GEMM_SMEM   (1024 + 3 * STAGE_BYTES)

template<int EPI_F16>
__global__ __launch_bounds__(256, 2)
void gemm_mma1(const __half* __restrict__ Ah,
               const __half* __restrict__ Bw,
               const float* __restrict__ bias,
               float* __restrict__ Cf, __half* __restrict__ Ch,
               int K, int a_mul, int a_shift, int Ntot)
{
    extern __shared__ char smem[];
    const uint32_t su = smem_to_u32(smem);
    const int tid  = threadIdx.x;
    const int wid  = tid >> 5;
    const int lane = tid & 31;
    const int e  = blockIdx.z;
    const int m0 = blockIdx.y * 128;
    const int n0 = blockIdx.x * 128;
    const int warp_m = wid & 3;     // 4 warps in m
    const int warp_n = wid >> 2;    // 2 warps in n
    const int esel = e >> a_shift;

    if (tid < 128)
        ((float*)smem)[tid] = bias[(size_t)e * Ntot + n0 + tid];

    // ---- stage loader (cp.async), BK=64 ----
    // A tile (@0):     128 rows x 64 k (128B rows, 8 chunks), swizzle ac ^ (row&7)
    // B tile (@16384): 64 k-rows x 128 n (256B rows, 16 chunks), swizzle nc ^ (krow&7)
    auto load_stage = [&](int s, int k0) {
        uint32_t st = su + 1024 + s * STAGE_BYTES;
        #pragma unroll
        for (int t = 0; t < 4; ++t) {
            int idx = tid + t * 256;
            int arow = idx >> 3, ac = idx & 7;
            size_t aoff = ((size_t)(m0 + arow) * a_mul + esel) * K + k0 + ac * 8;
            uint32_t ad = arow * 128 + ((ac ^ (arow & 7)) << 4);
            CP_ASYNC16(st + ad, Ah + aoff);
            int krow = idx >> 4, nc = idx & 15;
            size_t boff = ((size_t)e * K + k0 + krow) * Ntot + n0 + nc * 8;
            uint32_t bd = krow * 256 + ((nc ^ (krow & 7)) << 4);
            CP_ASYNC16(st + 16384 + bd, Bw + boff);
        }
        CP_COMMIT();
    };

    float c[2][8][4];
    #pragma unroll
    for (int i = 0; i < 2; i++)
        #pragma unroll
        for (int j = 0; j < 8; j++)
            #pragma unroll
            for (int q = 0; q < 4; q++) c[i][j][q] = 0.f;

    const int nk = K >> 6;
    load_stage(0, 0);
    load_stage(1, 64);

    const int a_rl   = (lane & 7) + ((lane >> 3) & 1) * 8;
    const int a_kc_h = lane >> 4;
    const int b_kl   = (lane & 7) + ((lane >> 3) & 1) * 8;
    const int b_nc_h = lane >> 4;

    int s = 0;
    for (int cIt = 0; cIt < nk; ++cIt) {
        CP_WAIT1();            // this thread's stage-cIt copies done
        __syncthreads();       // ALL threads' copies visible; prior compute drained
        if (cIt + 2 < nk) {
            int sn = s + 2;
            if (sn >= 3) sn -= 3;
            load_stage(sn, (cIt + 2) << 6);
        } else {
            CP_COMMIT();
        }

        uint32_t st = su + 1024 + s * STAGE_BYTES;
        #pragma unroll
        for (int ks = 0; ks < 4; ++ks) {
            uint32_t ah[2][4];
            #pragma unroll
            for (int mi = 0; mi < 2; ++mi) {
                int row = warp_m * 32 + mi * 16 + a_rl;
                int kc  = ks * 2 + a_kc_h;
                uint32_t ad = st + row * 128 + ((kc ^ (row & 7)) << 4);
                LDSM_X4(ah[mi], ad);
            }
            uint32_t bw[4][4];
            #pragma unroll
            for (int ni = 0; ni < 4; ++ni) {
                int krow = ks * 16 + b_kl;
                int nc   = warp_n * 8 + ni * 2 + b_nc_h;
                uint32_t bd = st + 16384 + krow * 256 + ((nc ^ (krow & 7)) << 4);
                LDSM_X4T(bw[ni], bd);
            }
            #pragma unroll
            for (int mi = 0; mi < 2; ++mi)
                #pragma unroll
                for (int ni = 0; ni < 4; ++ni)
                    #pragma unroll
                    for (int h = 0; h < 2; ++h)
                        MMA16816H(c[mi][ni * 2 + h], ah[mi], bw[ni][h * 2], bw[ni][h * 2 + 1]);
        }
        s = (s == 2) ? 0 : s + 1;
    }

    // ---- epilogue ----
    const float* bs = (const float*)smem;
    #pragma unroll
    for (int mi = 0; mi < 2; ++mi) {
        int r0 = m0 + warp_m * 32 + mi * 16 + (lane >> 2);
        #pragma unroll
        for (int h2 = 0; h2 < 2; ++h2) {
            int row = r0 + h2 * 8;
            size_t cbase = ((size_t)row * E_SZ + e) * Ntot;
            #pragma unroll
            for (int nj = 0; nj < 8; ++nj) {
                int col = warp_n * 64 + nj * 8 + (lane & 3) * 2;
                float v0 = c[mi][nj][h2 * 2]     + bs[col];
                float v1 = c[mi][nj][h2 * 2 + 1] + bs[col + 1];
                if (EPI_F16) {
                    v0 = fmaxf(v0, 0.f); v1 = fmaxf(v1, 0.f);
                    __half2 hp = {__float2half_rn(v0), __float2half_rn(v1)};
                    *(uint32_t*)(Ch + cbase + n0 + col) = *(uint32_t*)&hp;
                } else {
                    *(float2*)(Cf + cbase + n0 + col) = make_float2(v0, v1);
                }
            }
        }
    }
}

// ==================== gate: softmax(x[:, :M] @ Wg + bg) + add ====================
__global__ __launch_bounds__(256)
void gate_kernel(const float* __restrict__ x,
                 const float* __restrict__ Wg,
                 const float* __restrict__ bg,
                 const float* __restrict__ sew_task,
                 const float* __restrict__ sew_shared,
                 float* __restrict__ G,
                 int M, int layer)
{
    __shared__ float xs[8][D_SZ];
    const int wl   = threadIdx.x >> 5;
    const int lane = threadIdx.x & 31;
    const int wg   = blockIdx.x * 8 + wl;
    if (wg >= B_SZ * M) return;
    const int b = wg / M;
    const int m = wg - b * M;

    const float* xr = x + ((size_t)b * 9 + m) * D_SZ;
    for (int k = lane; k < D_SZ; k += 32) xs[wl][k] = xr[k];
    __syncwarp();

    float acc = 0.f;
    if (lane < E_SZ) {
        const float* w = Wg + (size_t)m * D_SZ * E_SZ + lane;
        #pragma unroll 4
        for (int k = 0; k < D_SZ; k++)
            acc += xs[wl][k] * w[(size_t)k * E_SZ];
        acc += bg[m * E_SZ + lane];
    }
    float v = (lane < E_SZ) ? acc : -3.4e38f;
    float mx = v;
    #pragma unroll
    for (int o = 16; o > 0; o >>= 1)
        mx = fmaxf(mx, __shfl_xor_sync(0xffffffffu, mx, o));
    float ex = (lane < E_SZ) ? expf(v - mx) : 0.f;
    float s = ex;
    #pragma unroll
    for (int o = 16; o > 0; o >>= 1)
        s += __shfl_xor_sync(0xffffffffu, s, o);

    if (lane < E_SZ) {
        float g = ex / s;
        float addv = 0.f;
        if (layer == 0) {
            if (m < T_SZ && (lane >> 1) == m) addv = sew_task[m * 4 + (lane & 1)];
            if (m == T_SZ && lane >= 16)      addv = sew_shared[lane - 16];
        } else {
            if ((lane >> 1) == m)             addv = sew_task[m * 4 + 2 + (lane & 1)];
        }
        G[((size_t)b * M + m) * E_SZ + lane] = g + addv;
    }
}

// ==================== combine: out[b,m,:] = sum_e G[b,m,e] * EO[b,e,:] ====================
__global__ __launch_bounds__(256)
void combine_kernel(const float* __restrict__ EO,
                    const float* __restrict__ G,
                    float* __restrict__ OUT,
                    __half* __restrict__ OH,
                    int M)
{
    __shared__ float gs[9 * E_SZ];
    const int b   = blockIdx.x;
    const int tid = threadIdx.x;
    if (tid < M * E_SZ) gs[tid] = G[(size_t)b * M * E_SZ + tid];
    __syncthreads();

    const float* eo = EO + (size_t)b * E_SZ * D_SZ;
    for (int d = tid; d < D_SZ; d += 256) {
        float ev[E_SZ];
        #pragma unroll
        for (int e2 = 0; e2 < E_SZ; e2++)
            ev[e2] = eo[(size_t)e2 * D_SZ + d];
        for (int m = 0; m < M; m++) {
            float s = 0.f;
            #pragma unroll
            for (int e2 = 0; e2 < E_SZ; e2++)
                s += gs[m * E_SZ + e2] * ev[e2];
            if (OH) {
                size_t o = ((size_t)b * 9 + m) * D_SZ + d;   // pitch-9 for layer chaining
                OUT[o] = s;
                OH[o]  = __float2half_rn(s);
            } else {
                OUT[((size_t)b * M + m) * D_SZ + d] = s;     // final (B,8,D) contiguous
            }
        }
    }
}

// ==================== launcher ====================
extern "C" void kernel_launch(void* const* d_in, const int* in_sizes, int n_in,
                              void* d_out, int out_size)
{
    const float* x_in  = (const float*)d_in[0];
    const float* W1_0  = (const float*)d_in[1];
    const float* b1_0  = (const float*)d_in[2];
    const float* W2_0  = (const float*)d_in[3];
    const float* b2_0  = (const float*)d_in[4];
    const float* Wg_0  = (const float*)d_in[5];
    const float* bg_0  = (const float*)d_in[6];
    const float* W1_1  = (const float*)d_in[7];
    const float* b1_1  = (const float*)d_in[8];
    const float* W2_1  = (const float*)d_in[9];
    const float* b2_1  = (const float*)d_in[10];
    const float* Wg_1  = (const float*)d_in[11];
    const float* bg_1  = (const float*)d_in[12];
    const float* sewt  = (const float*)d_in[13];
    const float* sews  = (const float*)d_in[14];
    float* out = (float*)d_out;

    __half *xh, *w, *h1, *x1h;
    float *eo, *x1, *Gp;
    cudaGetSymbolAddress((void**)&xh,  g_xh);
    cudaGetSymbolAddress((void**)&w,   g_w);
    cudaGetSymbolAddress((void**)&h1,  g_h1);
    cudaGetSymbolAddress((void**)&eo,  g_eo);
    cudaGetSymbolAddress((void**)&x1,  g_x1);
    cudaGetSymbolAddress((void**)&x1h, g_x1h);
    cudaGetSymbolAddress((void**)&Gp,  g_G);

    cudaFuncSetAttribute(gemm_mma1<1>, cudaFuncAttributeMaxDynamicSharedMemorySize, GEMM_SMEM);
    cudaFuncSetAttribute(gemm_mma1<0>, cudaFuncAttributeMaxDynamicSharedMemorySize, GEMM_SMEM);

    // ---- prep: fp16 converts ----
    int n4x = B_SZ * 9 * D_SZ / 4;
    conv_f32h<<<(n4x/2 + 255) / 256, 256>>>(x_in, xh, n4x);
    int n4w = WT_ONE / 4;
    int gw = (n4w/2 + 255) / 256;
    conv_f32h<<<gw, 256>>>(W1_0, w + 0*WT_ONE, n4w);
    conv_f32h<<<gw, 256>>>(W2_0, w + 1*WT_ONE, n4w);
    conv_f32h<<<gw, 256>>>(W1_1, w + 2*WT_ONE, n4w);
    conv_f32h<<<gw, 256>>>(W2_1, w + 3*WT_ONE, n4w);

    dim3 g1(H_SZ / 128, B_SZ / 128, E_SZ);   // (8, 8, 18)
    dim3 g2(D_SZ / 128, B_SZ / 128, E_SZ);   // (4, 8, 18)

    // ---- layer 0 ----
    gemm_mma1<1><<<g1, 256, GEMM_SMEM>>>(xh, w + 0*WT_ONE, b1_0,
                                         nullptr, h1, D_SZ, 9, 1, H_SZ);
    gemm_mma1<0><<<g2, 256, GEMM_SMEM>>>(h1, w + 1*WT_ONE, b2_0,
                                         eo, nullptr, H_SZ, E_SZ, 0, D_SZ);
    gate_kernel<<<(B_SZ * 9 + 7) / 8, 256>>>(x_in, Wg_0, bg_0, sewt, sews, Gp, 9, 0);
    combine_kernel<<<B_SZ, 256>>>(eo, Gp, x1, x1h, 9);

    // ---- layer 1 ----
    gemm_mma1<1><<<g1, 256, GEMM_SMEM>>>(x1h, w + 2*WT_ONE, b1_1,
                                         nullptr, h1, D_SZ, 9, 1, H_SZ);
    gemm_mma1<0><<<g2, 256, GEMM_SMEM>>>(h1, w + 3*WT_ONE, b2_1,
                                         eo, nullptr, H_SZ, E_SZ, 0, D_SZ);
    gate_kernel<<<(B_SZ * 8 + 7) / 8, 256>>>(x1, Wg_1, bg_1, sewt, sews, Gp, 8, 1);
    combine_kernel<<<B_SZ, 256>>>(eo, Gp, out, nullptr, 8);
}

// round 9
// speedup vs baseline: 5.7183x; 1.0482x over previous
#include <cuda_runtime.h>
#include <cuda_fp16.h>
#include <cstdint>
#include <math.h>

// Problem constants
#define B_SZ 1024
#define D_SZ 512
#define H_SZ 1024
#define T_SZ 8
#define E_SZ 18

// ==================== PTX helpers ====================
__device__ __forceinline__ uint32_t smem_to_u32(const void* p) {
    uint32_t a;
    asm("{ .reg .u64 t; cvta.to.shared.u64 t, %1; cvt.u32.u64 %0, t; }" : "=r"(a) : "l"(p));
    return a;
}
#define CP_ASYNC16(dst, src) \
    asm volatile("cp.async.cg.shared.global [%0], [%1], 16;" :: "r"(dst), "l"(src))
#define CP_COMMIT() asm volatile("cp.async.commit_group;" ::: "memory")
#define CP_WAIT1()  asm volatile("cp.async.wait_group 1;" ::: "memory")

#define LDSM_X4(r, a) \
    asm volatile("ldmatrix.sync.aligned.m8n8.x4.shared.b16 {%0,%1,%2,%3}, [%4];" \
        : "=r"((r)[0]), "=r"((r)[1]), "=r"((r)[2]), "=r"((r)[3]) : "r"(a))
#define LDSM_X4T(r, a) \
    asm volatile("ldmatrix.sync.aligned.m8n8.x4.trans.shared.b16 {%0,%1,%2,%3}, [%4];" \
        : "=r"((r)[0]), "=r"((r)[1]), "=r"((r)[2]), "=r"((r)[3]) : "r"(a))

// f16 mma, fp32 accumulate
#define MMA16816H(c, a, b0, b1) \
    asm volatile("mma.sync.aligned.m16n8k16.row.col.f32.f16.f16.f32 " \
        "{%0,%1,%2,%3}, {%4,%5,%6,%7}, {%8,%9}, {%0,%1,%2,%3};" \
        : "+f"((c)[0]), "+f"((c)[1]), "+f"((c)[2]), "+f"((c)[3]) \
        : "r"((a)[0]), "r"((a)[1]), "r"((a)[2]), "r"((a)[3]), "r"(b0), "r"(b1))

// ==================== scratch (static device globals) ====================
__device__ __half g_xh [B_SZ * 9 * D_SZ];
#define WT_ONE (E_SZ * H_SZ * D_SZ)            // 9,437,184 elems per weight tensor
__device__ __half g_w[4 * WT_ONE];             // (E,K,N) native layout fp16
__device__ __half g_h1 [B_SZ * E_SZ * H_SZ];
__device__ float  g_eo [B_SZ * E_SZ * D_SZ];
__device__ float  g_x1 [B_SZ * 9 * D_SZ];
__device__ __half g_x1h[B_SZ * 9 * D_SZ];
__device__ float  g_G  [B_SZ * 9 * E_SZ];

// ==================== prep: fp32 -> fp16 convert, simple (for x) ====================
__global__ __launch_bounds__(256)
void conv_f32h(const float* __restrict__ X, __half* __restrict__ H, int n4)
{
    int i0 = (blockIdx.x * blockDim.x + threadIdx.x) * 2;
    #pragma unroll
    for (int u = 0; u < 2; ++u) {
        int i = i0 + u;
        if (i >= n4) return;
        float4 v = ((const float4*)X)[i];
        __half2 hp0 = {__float2half_rn(v.x), __float2half_rn(v.y)};
        __half2 hp1 = {__float2half_rn(v.z), __float2half_rn(v.w)};
        ((__half2*)H)[2*i]   = hp0;
        ((__half2*)H)[2*i+1] = hp1;
    }
}

// ==================== prep: batched weight convert, 16B stores, 2x ILP ==============
// grid.y selects source tensor; dest = g_w + y*WT_ONE. n8 = WT_ONE/8.
__global__ __launch_bounds__(256)
void conv_w4(const float* __restrict__ W0, const float* __restrict__ W1,
             const float* __restrict__ W2, const float* __restrict__ W3,
             __half* __restrict__ Hbase, int n8)
{
    const float* src = (blockIdx.y == 0) ? W0 : (blockIdx.y == 1) ? W1
                     : (blockIdx.y == 2) ? W2 : W3;
    __half* dst = Hbase + (size_t)blockIdx.y * WT_ONE;
    int i0 = (blockIdx.x * blockDim.x + threadIdx.x) * 2;
    #pragma unroll
    for (int u = 0; u < 2; ++u) {
        int i = i0 + u;                      // 8-element chunk index
        if (i >= n8) return;
        float4 v0 = ((const float4*)src)[2*i];
        float4 v1 = ((const float4*)src)[2*i + 1];
        __half2 a = {__float2half_rn(v0.x), __float2half_rn(v0.y)};
        __half2 b = {__float2half_rn(v0.z), __float2half_rn(v0.w)};
        __half2 c = {__float2half_rn(v1.x), __float2half_rn(v1.y)};
        __half2 d = {__float2half_rn(v1.z), __float2half_rn(v1.w)};
        uint4 o;
        o.x = *(uint32_t*)&a; o.y = *(uint32_t*)&b;
        o.z = *(uint32_t*)&c; o.w = *(uint32_t*)&d;
        ((uint4*)dst)[i] = o;
    }
}

// ==================== GEMM: mma.sync fp16, 64x64 warp tiles ====================
// C[m,e,n] (pitch 18*Ntot) = act( sum_k A[(m*a_mul+(e>>a_shift)), k] * W[e, k, n] + bias[e,n] )
// 128x128 CTA tile, BK=64, 3-stage cp.async (wait -> sync -> load -> compute).
// 4 warps (2m x 2n), warp tile 64x64: 8 LDSM per 32 MMA. 2 CTAs/SM.
#define STAGE_BYTES 32768
#define GEMM_SMEM   (1024 + 3 * STAGE_BYTES)

template<int EPI_F16>
__global__ __launch_bounds__(128, 2)
void gemm_mma1(const __half* __restrict__ Ah,
               const __half* __restrict__ Bw,
               const float* __restrict__ bias,
               float* __restrict__ Cf, __half* __restrict__ Ch,
               int K, int a_mul, int a_shift, int Ntot)
{
    extern __shared__ char smem[];
    const uint32_t su = smem_to_u32(smem);
    const int tid  = threadIdx.x;
    const int wid  = tid >> 5;
    const int lane = tid & 31;
    const int e  = blockIdx.z;
    const int m0 = blockIdx.y * 128;
    const int n0 = blockIdx.x * 128;
    const int warp_m = wid & 1;     // 2 warps in m (64 rows each)
    const int warp_n = wid >> 1;    // 2 warps in n (64 cols each)
    const int esel = e >> a_shift;

    if (tid < 128)
        ((float*)smem)[tid] = bias[(size_t)e * Ntot + n0 + tid];

    // ---- stage loader (cp.async), BK=64, 128 threads ----
    // A tile (@0):     128 rows x 64 k (128B rows, 8 chunks), swizzle ac ^ (row&7)
    // B tile (@16384): 64 k-rows x 128 n (256B rows, 16 chunks), swizzle nc ^ (krow&7)
    auto load_stage = [&](int s, int k0) {
        uint32_t st = su + 1024 + s * STAGE_BYTES;
        #pragma unroll
        for (int t = 0; t < 8; ++t) {
            int idx = tid + t * 128;
            int arow = idx >> 3, ac = idx & 7;
            size_t aoff = ((size_t)(m0 + arow) * a_mul + esel) * K + k0 + ac * 8;
            uint32_t ad = arow * 128 + ((ac ^ (arow & 7)) << 4);
            CP_ASYNC16(st + ad, Ah + aoff);
            int krow = idx >> 4, nc = idx & 15;
            size_t boff = ((size_t)e * K + k0 + krow) * Ntot + n0 + nc * 8;
            uint32_t bd = krow * 256 + ((nc ^ (krow & 7)) << 4);
            CP_ASYNC16(st + 16384 + bd, Bw + boff);
        }
        CP_COMMIT();
    };

    float c[4][8][4];
    #pragma unroll
    for (int i = 0; i < 4; i++)
        #pragma unroll
        for (int j = 0; j < 8; j++)
            #pragma unroll
            for (int q = 0; q < 4; q++) c[i][j][q] = 0.f;

    const int nk = K >> 6;
    load_stage(0, 0);
    load_stage(1, 64);

    const int a_rl   = (lane & 7) + ((lane >> 3) & 1) * 8;
    const int a_kc_h = lane >> 4;
    const int b_kl   = (lane & 7) + ((lane >> 3) & 1) * 8;
    const int b_nc_h = lane >> 4;

    int s = 0;
    for (int cIt = 0; cIt < nk; ++cIt) {
        CP_WAIT1();            // this thread's stage-cIt copies done
        __syncthreads();       // ALL threads' copies visible; prior compute drained
        if (cIt + 2 < nk) {
            int sn = s + 2;
            if (sn >= 3) sn -= 3;
            load_stage(sn, (cIt + 2) << 6);
        } else {
            CP_COMMIT();
        }

        uint32_t st = su + 1024 + s * STAGE_BYTES;
        #pragma unroll
        for (int ks = 0; ks < 4; ++ks) {
            uint32_t ah[4][4];
            #pragma unroll
            for (int mi = 0; mi < 4; ++mi) {
                int row = warp_m * 64 + mi * 16 + a_rl;
                int kc  = ks * 2 + a_kc_h;
                uint32_t ad = st + row * 128 + ((kc ^ (row & 7)) << 4);
                LDSM_X4(ah[mi], ad);
            }
            uint32_t bw[4][4];
            #pragma unroll
            for (int ni = 0; ni < 4; ++ni) {
                int krow = ks * 16 + b_kl;
                int nc   = warp_n * 8 + ni * 2 + b_nc_h;
                uint32_t bd = st + 16384 + krow * 256 + ((nc ^ (krow & 7)) << 4);
                LDSM_X4T(bw[ni], bd);
            }
            #pragma unroll
            for (int mi = 0; mi < 4; ++mi)
                #pragma unroll
                for (int ni = 0; ni < 4; ++ni)
                    #pragma unroll
                    for (int h = 0; h < 2; ++h)
                        MMA16816H(c[mi][ni * 2 + h], ah[mi], bw[ni][h * 2], bw[ni][h * 2 + 1]);
        }
        s = (s == 2) ? 0 : s + 1;
    }

    // ---- epilogue ----
    const float* bs = (const float*)smem;
    #pragma unroll
    for (int mi = 0; mi < 4; ++mi) {
        int r0 = m0 + warp_m * 64 + mi * 16 + (lane >> 2);
        #pragma unroll
        for (int h2 = 0; h2 < 2; ++h2) {
            int row = r0 + h2 * 8;
            size_t cbase = ((size_t)row * E_SZ + e) * Ntot;
            #pragma unroll
            for (int nj = 0; nj < 8; ++nj) {
                int col = warp_n * 64 + nj * 8 + (lane & 3) * 2;
                float v0 = c[mi][nj][h2 * 2]     + bs[col];
                float v1 = c[mi][nj][h2 * 2 + 1] + bs[col + 1];
                if (EPI_F16) {
                    v0 = fmaxf(v0, 0.f); v1 = fmaxf(v1, 0.f);
                    __half2 hp = {__float2half_rn(v0), __float2half_rn(v1)};
                    *(uint32_t*)(Ch + cbase + n0 + col) = *(uint32_t*)&hp;
                } else {
                    *(float2*)(Cf + cbase + n0 + col) = make_float2(v0, v1);
                }
            }
        }
    }
}

// ==================== gate: softmax(x[:, :M] @ Wg + bg) + add ====================
__global__ __launch_bounds__(256)
void gate_kernel(const float* __restrict__ x,
                 const float* __restrict__ Wg,
                 const float* __restrict__ bg,
                 const float* __restrict__ sew_task,
                 const float* __restrict__ sew_shared,
                 float* __restrict__ G,
                 int M, int layer)
{
    __shared__ float xs[8][D_SZ];
    const int wl   = threadIdx.x >> 5;
    const int lane = threadIdx.x & 31;
    const int wg   = blockIdx.x * 8 + wl;
    if (wg >= B_SZ * M) return;
    const int b = wg / M;
    const int m = wg - b * M;

    const float* xr = x + ((size_t)b * 9 + m) * D_SZ;
    for (int k = lane; k < D_SZ; k += 32) xs[wl][k] = xr[k];
    __syncwarp();

    float acc = 0.f;
    if (lane < E_SZ) {
        const float* w = Wg + (size_t)m * D_SZ * E_SZ + lane;
        #pragma unroll 4
        for (int k = 0; k < D_SZ; k++)
            acc += xs[wl][k] * w[(size_t)k * E_SZ];
        acc += bg[m * E_SZ + lane];
    }
    float v = (lane < E_SZ) ? acc : -3.4e38f;
    float mx = v;
    #pragma unroll
    for (int o = 16; o > 0; o >>= 1)
        mx = fmaxf(mx, __shfl_xor_sync(0xffffffffu, mx, o));
    float ex = (lane < E_SZ) ? expf(v - mx) : 0.f;
    float s = ex;
    #pragma unroll
    for (int o = 16; o > 0; o >>= 1)
        s += __shfl_xor_sync(0xffffffffu, s, o);

    if (lane < E_SZ) {
        float g = ex / s;
        float addv = 0.f;
        if (layer == 0) {
            if (m < T_SZ && (lane >> 1) == m) addv = sew_task[m * 4 + (lane & 1)];
            if (m == T_SZ && lane >= 16)      addv = sew_shared[lane - 16];
        } else {
            if ((lane >> 1) == m)             addv = sew_task[m * 4 + 2 + (lane & 1)];
        }
        G[((size_t)b * M + m) * E_SZ + lane] = g + addv;
    }
}

// ==================== combine: out[b,m,:] = sum_e G[b,m,e] * EO[b,e,:] ====================
__global__ __launch_bounds__(256)
void combine_kernel(const float* __restrict__ EO,
                    const float* __restrict__ G,
                    float* __restrict__ OUT,
                    __half* __restrict__ OH,
                    int M)
{
    __shared__ float gs[9 * E_SZ];
    const int b   = blockIdx.x;
    const int tid = threadIdx.x;
    if (tid < M * E_SZ) gs[tid] = G[(size_t)b * M * E_SZ + tid];
    __syncthreads();

    const float* eo = EO + (size_t)b * E_SZ * D_SZ;
    for (int d = tid; d < D_SZ; d += 256) {
        float ev[E_SZ];
        #pragma unroll
        for (int e2 = 0; e2 < E_SZ; e2++)
            ev[e2] = eo[(size_t)e2 * D_SZ + d];
        for (int m = 0; m < M; m++) {
            float s = 0.f;
            #pragma unroll
            for (int e2 = 0; e2 < E_SZ; e2++)
                s += gs[m * E_SZ + e2] * ev[e2];
            if (OH) {
                size_t o = ((size_t)b * 9 + m) * D_SZ + d;   // pitch-9 for layer chaining
                OUT[o] = s;
                OH[o]  = __float2half_rn(s);
            } else {
                OUT[((size_t)b * M + m) * D_SZ + d] = s;     // final (B,8,D) contiguous
            }
        }
    }
}

// ==================== launcher ====================
extern "C" void kernel_launch(void* const* d_in, const int* in_sizes, int n_in,
                              void* d_out, int out_size)
{
    const float* x_in  = (const float*)d_in[0];
    const float* W1_0  = (const float*)d_in[1];
    const float* b1_0  = (const float*)d_in[2];
    const float* W2_0  = (const float*)d_in[3];
    const float* b2_0  = (const float*)d_in[4];
    const float* Wg_0  = (const float*)d_in[5];
    const float* bg_0  = (const float*)d_in[6];
    const float* W1_1  = (const float*)d_in[7];
    const float* b1_1  = (const float*)d_in[8];
    const float* W2_1  = (const float*)d_in[9];
    const float* b2_1  = (const float*)d_in[10];
    const float* Wg_1  = (const float*)d_in[11];
    const float* bg_1  = (const float*)d_in[12];
    const float* sewt  = (const float*)d_in[13];
    const float* sews  = (const float*)d_in[14];
    float* out = (float*)d_out;

    __half *xh, *w, *h1, *x1h;
    float *eo, *x1, *Gp;
    cudaGetSymbolAddress((void**)&xh,  g_xh);
    cudaGetSymbolAddress((void**)&w,   g_w);
    cudaGetSymbolAddress((void**)&h1,  g_h1);
    cudaGetSymbolAddress((void**)&eo,  g_eo);
    cudaGetSymbolAddress((void**)&x1,  g_x1);
    cudaGetSymbolAddress((void**)&x1h, g_x1h);
    cudaGetSymbolAddress((void**)&Gp,  g_G);

    cudaFuncSetAttribute(gemm_mma1<1>, cudaFuncAttributeMaxDynamicSharedMemorySize, GEMM_SMEM);
    cudaFuncSetAttribute(gemm_mma1<0>, cudaFuncAttributeMaxDynamicSharedMemorySize, GEMM_SMEM);

    // ---- prep: fp16 converts ----
    int n4x = B_SZ * 9 * D_SZ / 4;
    conv_f32h<<<(n4x/2 + 255) / 256, 256>>>(x_in, xh, n4x);
    int n8w = WT_ONE / 8;
    dim3 gcw((n8w/2 + 255) / 256, 4);
    conv_w4<<<gcw, 256>>>(W1_0, W2_0, W1_1, W2_1, w, n8w);

    dim3 g1(H_SZ / 128, B_SZ / 128, E_SZ);   // (8, 8, 18)
    dim3 g2(D_SZ / 128, B_SZ / 128, E_SZ);   // (4, 8, 18)

    // ---- layer 0 ----
    gemm_mma1<1><<<g1, 128, GEMM_SMEM>>>(xh, w + 0*WT_ONE, b1_0,
                                         nullptr, h1, D_SZ, 9, 1, H_SZ);
    gemm_mma1<0><<<g2, 128, GEMM_SMEM>>>(h1, w + 1*WT_ONE, b2_0,
                                         eo, nullptr, H_SZ, E_SZ, 0, D_SZ);
    gate_kernel<<<(B_SZ * 9 + 7) / 8, 256>>>(x_in, Wg_0, bg_0, sewt, sews, Gp, 9, 0);
    combine_kernel<<<B_SZ, 256>>>(eo, Gp, x1, x1h, 9);

    // ---- layer 1 ----
    gemm_mma1<1><<<g1, 128, GEMM_SMEM>>>(x1h, w + 2*WT_ONE, b1_1,
                                         nullptr, h1, D_SZ, 9, 1, H_SZ);
    gemm_mma1<0><<<g2, 128, GEMM_SMEM>>>(h1, w + 3*WT_ONE, b2_1,
                                         eo, nullptr, H_SZ, E_SZ, 0, D_SZ);
    gate_kernel<<<(B_SZ * 8 + 7) / 8, 256>>>(x1, Wg_1, bg_1, sewt, sews, Gp, 8, 1);
    combine_kernel<<<B_SZ, 256>>>(eo, Gp, out, nullptr, 8);
}

// round 10
// speedup vs baseline: 5.7192x; 1.0002x over previous
#include <cuda_runtime.h>
#include <cuda_fp16.h>
#include <cstdint>
#include <math.h>

// Problem constants
#define B_SZ 1024
#define D_SZ 512
#define H_SZ 1024
#define T_SZ 8
#define E_SZ 18

// ==================== PTX helpers ====================
__device__ __forceinline__ uint32_t smem_to_u32(const void* p) {
    uint32_t a;
    asm("{ .reg .u64 t; cvta.to.shared.u64 t, %1; cvt.u32.u64 %0, t; }" : "=r"(a) : "l"(p));
    return a;
}
#define CP_ASYNC16(dst, src) \
    asm volatile("cp.async.cg.shared.global [%0], [%1], 16;" :: "r"(dst), "l"(src))
#define CP_COMMIT() asm volatile("cp.async.commit_group;" ::: "memory")
#define CP_WAIT1()  asm volatile("cp.async.wait_group 1;" ::: "memory")

#define LDSM_X4(r, a) \
    asm volatile("ldmatrix.sync.aligned.m8n8.x4.shared.b16 {%0,%1,%2,%3}, [%4];" \
        : "=r"((r)[0]), "=r"((r)[1]), "=r"((r)[2]), "=r"((r)[3]) : "r"(a))
#define LDSM_X4T(r, a) \
    asm volatile("ldmatrix.sync.aligned.m8n8.x4.trans.shared.b16 {%0,%1,%2,%3}, [%4];" \
        : "=r"((r)[0]), "=r"((r)[1]), "=r"((r)[2]), "=r"((r)[3]) : "r"(a))

// f16 mma, fp32 accumulate
#define MMA16816H(c, a, b0, b1) \
    asm volatile("mma.sync.aligned.m16n8k16.row.col.f32.f16.f16.f32 " \
        "{%0,%1,%2,%3}, {%4,%5,%6,%7}, {%8,%9}, {%0,%1,%2,%3};" \
        : "+f"((c)[0]), "+f"((c)[1]), "+f"((c)[2]), "+f"((c)[3]) \
        : "r"((a)[0]), "r"((a)[1]), "r"((a)[2]), "r"((a)[3]), "r"(b0), "r"(b1))

// ==================== scratch (static device globals) ====================
__device__ __half g_xh [B_SZ * 9 * D_SZ];
#define WT_ONE (E_SZ * H_SZ * D_SZ)            // 9,437,184 elems per weight tensor
__device__ __half g_w[4 * WT_ONE];             // (E,K,N) native layout fp16
__device__ __half g_h1 [B_SZ * E_SZ * H_SZ];
__device__ float  g_eo [B_SZ * E_SZ * D_SZ];
__device__ float  g_x1 [B_SZ * 9 * D_SZ];
__device__ __half g_x1h[B_SZ * 9 * D_SZ];

// ==================== prep: fp32 -> fp16 convert, simple (for x) ====================
__global__ __launch_bounds__(256)
void conv_f32h(const float* __restrict__ X, __half* __restrict__ H, int n4)
{
    int i0 = (blockIdx.x * blockDim.x + threadIdx.x) * 2;
    #pragma unroll
    for (int u = 0; u < 2; ++u) {
        int i = i0 + u;
        if (i >= n4) return;
        float4 v = ((const float4*)X)[i];
        __half2 hp0 = {__float2half_rn(v.x), __float2half_rn(v.y)};
        __half2 hp1 = {__float2half_rn(v.z), __float2half_rn(v.w)};
        ((__half2*)H)[2*i]   = hp0;
        ((__half2*)H)[2*i+1] = hp1;
    }
}

// ==================== prep: batched weight convert, MLP=4 ====================
// grid.y selects source tensor; dest = g_w + y*WT_ONE. n8 = WT_ONE/8 (8-elem chunks).
__global__ __launch_bounds__(256)
void conv_w4(const float* __restrict__ W0, const float* __restrict__ W1,
             const float* __restrict__ W2, const float* __restrict__ W3,
             __half* __restrict__ Hbase, int n8)
{
    const float* src = (blockIdx.y == 0) ? W0 : (blockIdx.y == 1) ? W1
                     : (blockIdx.y == 2) ? W2 : W3;
    __half* dst = Hbase + (size_t)blockIdx.y * WT_ONE;
    int i0 = (blockIdx.x * blockDim.x + threadIdx.x) * 4;

    // 8 independent 16B loads issued up-front (MLP=8)
    float4 v[8];
    #pragma unroll
    for (int u = 0; u < 4; ++u) {
        int i = i0 + u;
        if (i < n8) {
            v[2*u]   = ((const float4*)src)[2*i];
            v[2*u+1] = ((const float4*)src)[2*i + 1];
        }
    }
    #pragma unroll
    for (int u = 0; u < 4; ++u) {
        int i = i0 + u;
        if (i >= n8) return;
        __half2 a = {__float2half_rn(v[2*u].x), __float2half_rn(v[2*u].y)};
        __half2 b = {__float2half_rn(v[2*u].z), __float2half_rn(v[2*u].w)};
        __half2 c = {__float2half_rn(v[2*u+1].x), __float2half_rn(v[2*u+1].y)};
        __half2 d = {__float2half_rn(v[2*u+1].z), __float2half_rn(v[2*u+1].w)};
        uint4 o;
        o.x = *(uint32_t*)&a; o.y = *(uint32_t*)&b;
        o.z = *(uint32_t*)&c; o.w = *(uint32_t*)&d;
        ((uint4*)dst)[i] = o;
    }
}

// ==================== GEMM: mma.sync fp16, 64x64 warp tiles (unchanged, proven) ======
#define STAGE_BYTES 32768
#define GEMM_SMEM   (1024 + 3 * STAGE_BYTES)

template<int EPI_F16>
__global__ __launch_bounds__(128, 2)
void gemm_mma1(const __half* __restrict__ Ah,
               const __half* __restrict__ Bw,
               const float* __restrict__ bias,
               float* __restrict__ Cf, __half* __restrict__ Ch,
               int K, int a_mul, int a_shift, int Ntot)
{
    extern __shared__ char smem[];
    const uint32_t su = smem_to_u32(smem);
    const int tid  = threadIdx.x;
    const int wid  = tid >> 5;
    const int lane = tid & 31;
    const int e  = blockIdx.z;
    const int m0 = blockIdx.y * 128;
    const int n0 = blockIdx.x * 128;
    const int warp_m = wid & 1;     // 2 warps in m (64 rows each)
    const int warp_n = wid >> 1;    // 2 warps in n (64 cols each)
    const int esel = e >> a_shift;

    if (tid < 128)
        ((float*)smem)[tid] = bias[(size_t)e * Ntot + n0 + tid];

    auto load_stage = [&](int s, int k0) {
        uint32_t st = su + 1024 + s * STAGE_BYTES;
        #pragma unroll
        for (int t = 0; t < 8; ++t) {
            int idx = tid + t * 128;
            int arow = idx >> 3, ac = idx & 7;
            size_t aoff = ((size_t)(m0 + arow) * a_mul + esel) * K + k0 + ac * 8;
            uint32_t ad = arow * 128 + ((ac ^ (arow & 7)) << 4);
            CP_ASYNC16(st + ad, Ah + aoff);
            int krow = idx >> 4, nc = idx & 15;
            size_t boff = ((size_t)e * K + k0 + krow) * Ntot + n0 + nc * 8;
            uint32_t bd = krow * 256 + ((nc ^ (krow & 7)) << 4);
            CP_ASYNC16(st + 16384 + bd, Bw + boff);
        }
        CP_COMMIT();
    };

    float c[4][8][4];
    #pragma unroll
    for (int i = 0; i < 4; i++)
        #pragma unroll
        for (int j = 0; j < 8; j++)
            #pragma unroll
            for (int q = 0; q < 4; q++) c[i][j][q] = 0.f;

    const int nk = K >> 6;
    load_stage(0, 0);
    load_stage(1, 64);

    const int a_rl   = (lane & 7) + ((lane >> 3) & 1) * 8;
    const int a_kc_h = lane >> 4;
    const int b_kl   = (lane & 7) + ((lane >> 3) & 1) * 8;
    const int b_nc_h = lane >> 4;

    int s = 0;
    for (int cIt = 0; cIt < nk; ++cIt) {
        CP_WAIT1();            // this thread's stage-cIt copies done
        __syncthreads();       // ALL threads' copies visible; prior compute drained
        if (cIt + 2 < nk) {
            int sn = s + 2;
            if (sn >= 3) sn -= 3;
            load_stage(sn, (cIt + 2) << 6);
        } else {
            CP_COMMIT();
        }

        uint32_t st = su + 1024 + s * STAGE_BYTES;
        #pragma unroll
        for (int ks = 0; ks < 4; ++ks) {
            uint32_t ah[4][4];
            #pragma unroll
            for (int mi = 0; mi < 4; ++mi) {
                int row = warp_m * 64 + mi * 16 + a_rl;
                int kc  = ks * 2 + a_kc_h;
                uint32_t ad = st + row * 128 + ((kc ^ (row & 7)) << 4);
                LDSM_X4(ah[mi], ad);
            }
            uint32_t bw[4][4];
            #pragma unroll
            for (int ni = 0; ni < 4; ++ni) {
                int krow = ks * 16 + b_kl;
                int nc   = warp_n * 8 + ni * 2 + b_nc_h;
                uint32_t bd = st + 16384 + krow * 256 + ((nc ^ (krow & 7)) << 4);
                LDSM_X4T(bw[ni], bd);
            }
            #pragma unroll
            for (int mi = 0; mi < 4; ++mi)
                #pragma unroll
                for (int ni = 0; ni < 4; ++ni)
                    #pragma unroll
                    for (int h = 0; h < 2; ++h)
                        MMA16816H(c[mi][ni * 2 + h], ah[mi], bw[ni][h * 2], bw[ni][h * 2 + 1]);
        }
        s = (s == 2) ? 0 : s + 1;
    }

    // ---- epilogue ----
    const float* bs = (const float*)smem;
    #pragma unroll
    for (int mi = 0; mi < 4; ++mi) {
        int r0 = m0 + warp_m * 64 + mi * 16 + (lane >> 2);
        #pragma unroll
        for (int h2 = 0; h2 < 2; ++h2) {
            int row = r0 + h2 * 8;
            size_t cbase = ((size_t)row * E_SZ + e) * Ntot;
            #pragma unroll
            for (int nj = 0; nj < 8; ++nj) {
                int col = warp_n * 64 + nj * 8 + (lane & 3) * 2;
                float v0 = c[mi][nj][h2 * 2]     + bs[col];
                float v1 = c[mi][nj][h2 * 2 + 1] + bs[col + 1];
                if (EPI_F16) {
                    v0 = fmaxf(v0, 0.f); v1 = fmaxf(v1, 0.f);
                    __half2 hp = {__float2half_rn(v0), __float2half_rn(v1)};
                    *(uint32_t*)(Ch + cbase + n0 + col) = *(uint32_t*)&hp;
                } else {
                    *(float2*)(Cf + cbase + n0 + col) = make_float2(v0, v1);
                }
            }
        }
    }
}

// ==================== fused gate + combine ====================
// Block b: load x rows (M x 512) -> smem; logits (m,e) = dot + bg; softmax + sparse add;
// then out[b,m,:] = sum_e g[m,e] * EO[b,e,:].
// x: fp32, row (b,m) at b*9*512 + m*512 (both layers use pitch-9).
__global__ __launch_bounds__(256)
void fused_gate_combine(const float* __restrict__ x,
                        const float* __restrict__ Wg,
                        const float* __restrict__ bg,
                        const float* __restrict__ sew_task,   // (8,2,2)
                        const float* __restrict__ sew_shared, // (1,2)
                        const float* __restrict__ EO,
                        float* __restrict__ OUT,
                        __half* __restrict__ OH,
                        int M, int layer)
{
    __shared__ float xs[9 * D_SZ];     // 18 KB
    __shared__ float lg[9 * E_SZ];
    __shared__ float gs[9 * E_SZ];
    const int b   = blockIdx.x;
    const int tid = threadIdx.x;

    // load x rows
    for (int i = tid; i < M * D_SZ; i += 256)
        xs[i] = x[(size_t)b * 9 * D_SZ + i];
    __syncthreads();

    // logits: one thread per (m,e)
    if (tid < M * E_SZ) {
        int m = tid / E_SZ, e = tid - m * E_SZ;
        const float* xr = xs + m * D_SZ;
        const float* w  = Wg + (size_t)m * D_SZ * E_SZ + e;
        float a0 = 0.f, a1 = 0.f;
        #pragma unroll 4
        for (int k = 0; k < D_SZ; k += 2) {
            a0 += xr[k]     * w[(size_t)k * E_SZ];
            a1 += xr[k + 1] * w[(size_t)(k + 1) * E_SZ];
        }
        lg[tid] = a0 + a1 + bg[m * E_SZ + e];
    }
    __syncthreads();

    // softmax + sparse additive weights: one thread per m
    if (tid < M) {
        float mx = -3.4e38f;
        #pragma unroll
        for (int e = 0; e < E_SZ; e++) mx = fmaxf(mx, lg[tid * E_SZ + e]);
        float sum = 0.f;
        float ex[E_SZ];
        #pragma unroll
        for (int e = 0; e < E_SZ; e++) { ex[e] = expf(lg[tid * E_SZ + e] - mx); sum += ex[e]; }
        float inv = 1.f / sum;
        #pragma unroll
        for (int e = 0; e < E_SZ; e++) gs[tid * E_SZ + e] = ex[e] * inv;
        if (layer == 0) {
            if (tid < T_SZ) {
                gs[tid * E_SZ + 2 * tid]     += sew_task[tid * 4 + 0];
                gs[tid * E_SZ + 2 * tid + 1] += sew_task[tid * 4 + 1];
            } else {   // tid == 8 (shared)
                gs[tid * E_SZ + 16] += sew_shared[0];
                gs[tid * E_SZ + 17] += sew_shared[1];
            }
        } else {
            gs[tid * E_SZ + 2 * tid]     += sew_task[tid * 4 + 2];
            gs[tid * E_SZ + 2 * tid + 1] += sew_task[tid * 4 + 3];
        }
    }
    __syncthreads();

    // combine
    const float* eo = EO + (size_t)b * E_SZ * D_SZ;
    for (int d = tid; d < D_SZ; d += 256) {
        float ev[E_SZ];
        #pragma unroll
        for (int e2 = 0; e2 < E_SZ; e2++)
            ev[e2] = eo[(size_t)e2 * D_SZ + d];
        for (int m = 0; m < M; m++) {
            float s = 0.f;
            #pragma unroll
            for (int e2 = 0; e2 < E_SZ; e2++)
                s += gs[m * E_SZ + e2] * ev[e2];
            if (OH) {
                size_t o = ((size_t)b * 9 + m) * D_SZ + d;   // pitch-9 for layer chaining
                OUT[o] = s;
                OH[o]  = __float2half_rn(s);
            } else {
                OUT[((size_t)b * M + m) * D_SZ + d] = s;     // final (B,8,D) contiguous
            }
        }
    }
}

// ==================== launcher ====================
extern "C" void kernel_launch(void* const* d_in, const int* in_sizes, int n_in,
                              void* d_out, int out_size)
{
    const float* x_in  = (const float*)d_in[0];
    const float* W1_0  = (const float*)d_in[1];
    const float* b1_0  = (const float*)d_in[2];
    const float* W2_0  = (const float*)d_in[3];
    const float* b2_0  = (const float*)d_in[4];
    const float* Wg_0  = (const float*)d_in[5];
    const float* bg_0  = (const float*)d_in[6];
    const float* W1_1  = (const float*)d_in[7];
    const float* b1_1  = (const float*)d_in[8];
    const float* W2_1  = (const float*)d_in[9];
    const float* b2_1  = (const float*)d_in[10];
    const float* Wg_1  = (const float*)d_in[11];
    const float* bg_1  = (const float*)d_in[12];
    const float* sewt  = (const float*)d_in[13];
    const float* sews  = (const float*)d_in[14];
    float* out = (float*)d_out;

    __half *xh, *w, *h1, *x1h;
    float *eo, *x1;
    cudaGetSymbolAddress((void**)&xh,  g_xh);
    cudaGetSymbolAddress((void**)&w,   g_w);
    cudaGetSymbolAddress((void**)&h1,  g_h1);
    cudaGetSymbolAddress((void**)&eo,  g_eo);
    cudaGetSymbolAddress((void**)&x1,  g_x1);
    cudaGetSymbolAddress((void**)&x1h, g_x1h);

    cudaFuncSetAttribute(gemm_mma1<1>, cudaFuncAttributeMaxDynamicSharedMemorySize, GEMM_SMEM);
    cudaFuncSetAttribute(gemm_mma1<0>, cudaFuncAttributeMaxDynamicSharedMemorySize, GEMM_SMEM);

    // ---- prep: fp16 converts ----
    int n4x = B_SZ * 9 * D_SZ / 4;
    conv_f32h<<<(n4x/2 + 255) / 256, 256>>>(x_in, xh, n4x);
    int n8w = WT_ONE / 8;
    dim3 gcw((n8w/4 + 255) / 256, 4);
    conv_w4<<<gcw, 256>>>(W1_0, W2_0, W1_1, W2_1, w, n8w);

    dim3 g1(H_SZ / 128, B_SZ / 128, E_SZ);   // (8, 8, 18)
    dim3 g2(D_SZ / 128, B_SZ / 128, E_SZ);   // (4, 8, 18)

    // ---- layer 0 ----
    gemm_mma1<1><<<g1, 128, GEMM_SMEM>>>(xh, w + 0*WT_ONE, b1_0,
                                         nullptr, h1, D_SZ, 9, 1, H_SZ);
    gemm_mma1<0><<<g2, 128, GEMM_SMEM>>>(h1, w + 1*WT_ONE, b2_0,
                                         eo, nullptr, H_SZ, E_SZ, 0, D_SZ);
    fused_gate_combine<<<B_SZ, 256>>>(x_in, Wg_0, bg_0, sewt, sews, eo, x1, x1h, 9, 0);

    // ---- layer 1 ----
    gemm_mma1<1><<<g1, 128, GEMM_SMEM>>>(x1h, w + 2*WT_ONE, b1_1,
                                         nullptr, h1, D_SZ, 9, 1, H_SZ);
    gemm_mma1<0><<<g2, 128, GEMM_SMEM>>>(h1, w + 3*WT_ONE, b2_1,
                                         eo, nullptr, H_SZ, E_SZ, 0, D_SZ);
    fused_gate_combine<<<B_SZ, 256>>>(x1, Wg_1, bg_1, sewt, sews, eo, out, nullptr, 8, 1);
}

// round 11
// speedup vs baseline: 5.8509x; 1.0230x over previous
#include <cuda_runtime.h>
#include <cuda_fp16.h>
#include <cstdint>
#include <math.h>

// Problem constants
#define B_SZ 1024
#define D_SZ 512
#define H_SZ 1024
#define T_SZ 8
#define E_SZ 18

// ==================== PTX helpers ====================
__device__ __forceinline__ uint32_t smem_to_u32(const void* p) {
    uint32_t a;
    asm("{ .reg .u64 t; cvta.to.shared.u64 t, %1; cvt.u32.u64 %0, t; }" : "=r"(a) : "l"(p));
    return a;
}
#define CP_ASYNC16(dst, src) \
    asm volatile("cp.async.cg.shared.global [%0], [%1], 16;" :: "r"(dst), "l"(src))
#define CP_COMMIT() asm volatile("cp.async.commit_group;" ::: "memory")
#define CP_WAIT1()  asm volatile("cp.async.wait_group 1;" ::: "memory")

#define LDSM_X4(r, a) \
    asm volatile("ldmatrix.sync.aligned.m8n8.x4.shared.b16 {%0,%1,%2,%3}, [%4];" \
        : "=r"((r)[0]), "=r"((r)[1]), "=r"((r)[2]), "=r"((r)[3]) : "r"(a))
#define LDSM_X4T(r, a) \
    asm volatile("ldmatrix.sync.aligned.m8n8.x4.trans.shared.b16 {%0,%1,%2,%3}, [%4];" \
        : "=r"((r)[0]), "=r"((r)[1]), "=r"((r)[2]), "=r"((r)[3]) : "r"(a))

// f16 mma, fp32 accumulate
#define MMA16816H(c, a, b0, b1) \
    asm volatile("mma.sync.aligned.m16n8k16.row.col.f32.f16.f16.f32 " \
        "{%0,%1,%2,%3}, {%4,%5,%6,%7}, {%8,%9}, {%0,%1,%2,%3};" \
        : "+f"((c)[0]), "+f"((c)[1]), "+f"((c)[2]), "+f"((c)[3]) \
        : "r"((a)[0]), "r"((a)[1]), "r"((a)[2]), "r"((a)[3]), "r"(b0), "r"(b1))

// ==================== scratch (static device globals) ====================
__device__ __half g_xh [B_SZ * 9 * D_SZ];
#define WT_ONE (E_SZ * H_SZ * D_SZ)            // 9,437,184 elems per weight tensor
__device__ __half g_w[4 * WT_ONE];             // (E,K,N) native layout fp16
__device__ __half g_h1 [B_SZ * E_SZ * H_SZ];
__device__ float  g_eo [B_SZ * E_SZ * D_SZ];
__device__ float  g_x1 [B_SZ * 9 * D_SZ];
__device__ __half g_x1h[B_SZ * 9 * D_SZ];

// ==================== prep: fp32 -> fp16 convert, simple (for x) ====================
__global__ __launch_bounds__(256)
void conv_f32h(const float* __restrict__ X, __half* __restrict__ H, int n4)
{
    int i0 = (blockIdx.x * blockDim.x + threadIdx.x) * 2;
    #pragma unroll
    for (int u = 0; u < 2; ++u) {
        int i = i0 + u;
        if (i >= n4) return;
        float4 v = ((const float4*)X)[i];
        __half2 hp0 = {__float2half_rn(v.x), __float2half_rn(v.y)};
        __half2 hp1 = {__float2half_rn(v.z), __float2half_rn(v.w)};
        ((__half2*)H)[2*i]   = hp0;
        ((__half2*)H)[2*i+1] = hp1;
    }
}

// ==================== prep: single-tensor weight convert (W1_0 only) ====================
__global__ __launch_bounds__(256)
void conv_one(const float* __restrict__ src, __half* __restrict__ dst, int n8)
{
    int i0 = (blockIdx.x * blockDim.x + threadIdx.x) * 4;
    float4 v[8];
    #pragma unroll
    for (int u = 0; u < 4; ++u) {
        int i = i0 + u;
        if (i < n8) {
            v[2*u]   = ((const float4*)src)[2*i];
            v[2*u+1] = ((const float4*)src)[2*i + 1];
        }
    }
    #pragma unroll
    for (int u = 0; u < 4; ++u) {
        int i = i0 + u;
        if (i >= n8) return;
        __half2 a = {__float2half_rn(v[2*u].x), __float2half_rn(v[2*u].y)};
        __half2 b = {__float2half_rn(v[2*u].z), __float2half_rn(v[2*u].w)};
        __half2 c = {__float2half_rn(v[2*u+1].x), __float2half_rn(v[2*u+1].y)};
        __half2 d = {__float2half_rn(v[2*u+1].z), __float2half_rn(v[2*u+1].w)};
        uint4 o;
        o.x = *(uint32_t*)&a; o.y = *(uint32_t*)&b;
        o.z = *(uint32_t*)&c; o.w = *(uint32_t*)&d;
        ((uint4*)dst)[i] = o;
    }
}

// ==================== GEMM: mma.sync fp16, 64x64 warp tiles ====================
// CONV=1: grid is (8, 14, 18); CTAs with blockIdx.y >= 8 convert the other three
// weight tensors (interleaved with GEMM CTAs per z-plane for overlap).
#define STAGE_BYTES 32768
#define GEMM_SMEM   (1024 + 3 * STAGE_BYTES)

template<int EPI_F16, int CONV>
__global__ __launch_bounds__(128, 2)
void gemm_mma1(const __half* __restrict__ Ah,
               const __half* __restrict__ Bw,
               const float* __restrict__ bias,
               float* __restrict__ Cf, __half* __restrict__ Ch,
               int K, int a_mul, int a_shift, int Ntot,
               const float* __restrict__ C0, const float* __restrict__ C1,
               const float* __restrict__ C2, __half* __restrict__ Cd)
{
    if (CONV && blockIdx.y >= 8) {
        // converter CTA: 864 total = 3 tensors x 288 CTAs; 32 chunks (16B) per thread.
        int c = blockIdx.z * 48 + (blockIdx.y - 8) * 8 + blockIdx.x;   // [0, 864)
        int t = c / 288, local = c - t * 288;
        const float* src = (t == 0) ? C0 : (t == 1) ? C1 : C2;
        __half* dst = Cd + (size_t)t * WT_ONE;
        int base = local * 128 + threadIdx.x;                          // [0, 36864)
        #pragma unroll 4
        for (int j = 0; j < 32; ++j) {
            int i = j * 36864 + base;                                  // coalesced per warp
            float4 v0 = ((const float4*)src)[2*i];
            float4 v1 = ((const float4*)src)[2*i + 1];
            __half2 a = {__float2half_rn(v0.x), __float2half_rn(v0.y)};
            __half2 b = {__float2half_rn(v0.z), __float2half_rn(v0.w)};
            __half2 cc = {__float2half_rn(v1.x), __float2half_rn(v1.y)};
            __half2 d = {__float2half_rn(v1.z), __float2half_rn(v1.w)};
            uint4 o;
            o.x = *(uint32_t*)&a; o.y = *(uint32_t*)&b;
            o.z = *(uint32_t*)&cc; o.w = *(uint32_t*)&d;
            ((uint4*)dst)[i] = o;
        }
        return;
    }

    extern __shared__ char smem[];
    const uint32_t su = smem_to_u32(smem);
    const int tid  = threadIdx.x;
    const int wid  = tid >> 5;
    const int lane = tid & 31;
    const int e  = blockIdx.z;
    const int m0 = blockIdx.y * 128;
    const int n0 = blockIdx.x * 128;
    const int warp_m = wid & 1;     // 2 warps in m (64 rows each)
    const int warp_n = wid >> 1;    // 2 warps in n (64 cols each)
    const int esel = e >> a_shift;

    if (tid < 128)
        ((float*)smem)[tid] = bias[(size_t)e * Ntot + n0 + tid];

    auto load_stage = [&](int s, int k0) {
        uint32_t st = su + 1024 + s * STAGE_BYTES;
        #pragma unroll
        for (int t = 0; t < 8; ++t) {
            int idx = tid + t * 128;
            int arow = idx >> 3, ac = idx & 7;
            size_t aoff = ((size_t)(m0 + arow) * a_mul + esel) * K + k0 + ac * 8;
            uint32_t ad = arow * 128 + ((ac ^ (arow & 7)) << 4);
            CP_ASYNC16(st + ad, Ah + aoff);
            int krow = idx >> 4, nc = idx & 15;
            size_t boff = ((size_t)e * K + k0 + krow) * Ntot + n0 + nc * 8;
            uint32_t bd = krow * 256 + ((nc ^ (krow & 7)) << 4);
            CP_ASYNC16(st + 16384 + bd, Bw + boff);
        }
        CP_COMMIT();
    };

    float c[4][8][4];
    #pragma unroll
    for (int i = 0; i < 4; i++)
        #pragma unroll
        for (int j = 0; j < 8; j++)
            #pragma unroll
            for (int q = 0; q < 4; q++) c[i][j][q] = 0.f;

    const int nk = K >> 6;
    load_stage(0, 0);
    load_stage(1, 64);

    const int a_rl   = (lane & 7) + ((lane >> 3) & 1) * 8;
    const int a_kc_h = lane >> 4;
    const int b_kl   = (lane & 7) + ((lane >> 3) & 1) * 8;
    const int b_nc_h = lane >> 4;

    int s = 0;
    for (int cIt = 0; cIt < nk; ++cIt) {
        CP_WAIT1();            // this thread's stage-cIt copies done
        __syncthreads();       // ALL threads' copies visible; prior compute drained
        if (cIt + 2 < nk) {
            int sn = s + 2;
            if (sn >= 3) sn -= 3;
            load_stage(sn, (cIt + 2) << 6);
        } else {
            CP_COMMIT();
        }

        uint32_t st = su + 1024 + s * STAGE_BYTES;
        #pragma unroll
        for (int ks = 0; ks < 4; ++ks) {
            uint32_t ah[4][4];
            #pragma unroll
            for (int mi = 0; mi < 4; ++mi) {
                int row = warp_m * 64 + mi * 16 + a_rl;
                int kc  = ks * 2 + a_kc_h;
                uint32_t ad = st + row * 128 + ((kc ^ (row & 7)) << 4);
                LDSM_X4(ah[mi], ad);
            }
            uint32_t bw[4][4];
            #pragma unroll
            for (int ni = 0; ni < 4; ++ni) {
                int krow = ks * 16 + b_kl;
                int nc   = warp_n * 8 + ni * 2 + b_nc_h;
                uint32_t bd = st + 16384 + krow * 256 + ((nc ^ (krow & 7)) << 4);
                LDSM_X4T(bw[ni], bd);
            }
            #pragma unroll
            for (int mi = 0; mi < 4; ++mi)
                #pragma unroll
                for (int ni = 0; ni < 4; ++ni)
                    #pragma unroll
                    for (int h = 0; h < 2; ++h)
                        MMA16816H(c[mi][ni * 2 + h], ah[mi], bw[ni][h * 2], bw[ni][h * 2 + 1]);
        }
        s = (s == 2) ? 0 : s + 1;
    }

    // ---- epilogue ----
    const float* bs = (const float*)smem;
    #pragma unroll
    for (int mi = 0; mi < 4; ++mi) {
        int r0 = m0 + warp_m * 64 + mi * 16 + (lane >> 2);
        #pragma unroll
        for (int h2 = 0; h2 < 2; ++h2) {
            int row = r0 + h2 * 8;
            size_t cbase = ((size_t)row * E_SZ + e) * Ntot;
            #pragma unroll
            for (int nj = 0; nj < 8; ++nj) {
                int col = warp_n * 64 + nj * 8 + (lane & 3) * 2;
                float v0 = c[mi][nj][h2 * 2]     + bs[col];
                float v1 = c[mi][nj][h2 * 2 + 1] + bs[col + 1];
                if (EPI_F16) {
                    v0 = fmaxf(v0, 0.f); v1 = fmaxf(v1, 0.f);
                    __half2 hp = {__float2half_rn(v0), __float2half_rn(v1)};
                    *(uint32_t*)(Ch + cbase + n0 + col) = *(uint32_t*)&hp;
                } else {
                    *(float2*)(Cf + cbase + n0 + col) = make_float2(v0, v1);
                }
            }
        }
    }
}

// ==================== fused gate + combine ====================
__global__ __launch_bounds__(256)
void fused_gate_combine(const float* __restrict__ x,
                        const float* __restrict__ Wg,
                        const float* __restrict__ bg,
                        const float* __restrict__ sew_task,   // (8,2,2)
                        const float* __restrict__ sew_shared, // (1,2)
                        const float* __restrict__ EO,
                        float* __restrict__ OUT,
                        __half* __restrict__ OH,
                        int M, int layer)
{
    __shared__ float xs[9 * D_SZ];
    __shared__ float lg[9 * E_SZ];
    __shared__ float gs[9 * E_SZ];
    const int b   = blockIdx.x;
    const int tid = threadIdx.x;

    for (int i = tid; i < M * D_SZ; i += 256)
        xs[i] = x[(size_t)b * 9 * D_SZ + i];
    __syncthreads();

    if (tid < M * E_SZ) {
        int m = tid / E_SZ, e = tid - m * E_SZ;
        const float* xr = xs + m * D_SZ;
        const float* w  = Wg + (size_t)m * D_SZ * E_SZ + e;
        float a0 = 0.f, a1 = 0.f;
        #pragma unroll 4
        for (int k = 0; k < D_SZ; k += 2) {
            a0 += xr[k]     * w[(size_t)k * E_SZ];
            a1 += xr[k + 1] * w[(size_t)(k + 1) * E_SZ];
        }
        lg[tid] = a0 + a1 + bg[m * E_SZ + e];
    }
    __syncthreads();

    if (tid < M) {
        float mx = -3.4e38f;
        #pragma unroll
        for (int e = 0; e < E_SZ; e++) mx = fmaxf(mx, lg[tid * E_SZ + e]);
        float sum = 0.f;
        float ex[E_SZ];
        #pragma unroll
        for (int e = 0; e < E_SZ; e++) { ex[e] = expf(lg[tid * E_SZ + e] - mx); sum += ex[e]; }
        float inv = 1.f / sum;
        #pragma unroll
        for (int e = 0; e < E_SZ; e++) gs[tid * E_SZ + e] = ex[e] * inv;
        if (layer == 0) {
            if (tid < T_SZ) {
                gs[tid * E_SZ + 2 * tid]     += sew_task[tid * 4 + 0];
                gs[tid * E_SZ + 2 * tid + 1] += sew_task[tid * 4 + 1];
            } else {
                gs[tid * E_SZ + 16] += sew_shared[0];
                gs[tid * E_SZ + 17] += sew_shared[1];
            }
        } else {
            gs[tid * E_SZ + 2 * tid]     += sew_task[tid * 4 + 2];
            gs[tid * E_SZ + 2 * tid + 1] += sew_task[tid * 4 + 3];
        }
    }
    __syncthreads();

    const float* eo = EO + (size_t)b * E_SZ * D_SZ;
    for (int d = tid; d < D_SZ; d += 256) {
        float ev[E_SZ];
        #pragma unroll
        for (int e2 = 0; e2 < E_SZ; e2++)
            ev[e2] = eo[(size_t)e2 * D_SZ + d];
        for (int m = 0; m < M; m++) {
            float s = 0.f;
            #pragma unroll
            for (int e2 = 0; e2 < E_SZ; e2++)
                s += gs[m * E_SZ + e2] * ev[e2];
            if (OH) {
                size_t o = ((size_t)b * 9 + m) * D_SZ + d;
                OUT[o] = s;
                OH[o]  = __float2half_rn(s);
            } else {
                OUT[((size_t)b * M + m) * D_SZ + d] = s;
            }
        }
    }
}

// ==================== launcher ====================
extern "C" void kernel_launch(void* const* d_in, const int* in_sizes, int n_in,
                              void* d_out, int out_size)
{
    const float* x_in  = (const float*)d_in[0];
    const float* W1_0  = (const float*)d_in[1];
    const float* b1_0  = (const float*)d_in[2];
    const float* W2_0  = (const float*)d_in[3];
    const float* b2_0  = (const float*)d_in[4];
    const float* Wg_0  = (const float*)d_in[5];
    const float* bg_0  = (const float*)d_in[6];
    const float* W1_1  = (const float*)d_in[7];
    const float* b1_1  = (const float*)d_in[8];
    const float* W2_1  = (const float*)d_in[9];
    const float* b2_1  = (const float*)d_in[10];
    const float* Wg_1  = (const float*)d_in[11];
    const float* bg_1  = (const float*)d_in[12];
    const float* sewt  = (const float*)d_in[13];
    const float* sews  = (const float*)d_in[14];
    float* out = (float*)d_out;

    __half *xh, *w, *h1, *x1h;
    float *eo, *x1;
    cudaGetSymbolAddress((void**)&xh,  g_xh);
    cudaGetSymbolAddress((void**)&w,   g_w);
    cudaGetSymbolAddress((void**)&h1,  g_h1);
    cudaGetSymbolAddress((void**)&eo,  g_eo);
    cudaGetSymbolAddress((void**)&x1,  g_x1);
    cudaGetSymbolAddress((void**)&x1h, g_x1h);

    cudaFuncSetAttribute(gemm_mma1<1,1>, cudaFuncAttributeMaxDynamicSharedMemorySize, GEMM_SMEM);
    cudaFuncSetAttribute(gemm_mma1<1,0>, cudaFuncAttributeMaxDynamicSharedMemorySize, GEMM_SMEM);
    cudaFuncSetAttribute(gemm_mma1<0,0>, cudaFuncAttributeMaxDynamicSharedMemorySize, GEMM_SMEM);

    // ---- prep: only x and W1_0 on the critical path ----
    int n4x = B_SZ * 9 * D_SZ / 4;
    conv_f32h<<<(n4x/2 + 255) / 256, 256>>>(x_in, xh, n4x);
    int n8w = WT_ONE / 8;
    conv_one<<<(n8w/4 + 255) / 256, 256>>>(W1_0, w + 0*WT_ONE, n8w);

    dim3 g1c(H_SZ / 128, 14, E_SZ);          // (8, 14, 18): y<8 gemm, y>=8 convert W2_0/W1_1/W2_1
    dim3 g1(H_SZ / 128, B_SZ / 128, E_SZ);   // (8, 8, 18)
    dim3 g2(D_SZ / 128, B_SZ / 128, E_SZ);   // (4, 8, 18)

    // ---- layer 0 (gemm1 also converts the remaining 3 weight tensors, overlapped) ----
    gemm_mma1<1,1><<<g1c, 128, GEMM_SMEM>>>(xh, w + 0*WT_ONE, b1_0,
                                            nullptr, h1, D_SZ, 9, 1, H_SZ,
                                            W2_0, W1_1, W2_1, w + 1*WT_ONE);
    gemm_mma1<0,0><<<g2, 128, GEMM_SMEM>>>(h1, w + 1*WT_ONE, b2_0,
                                           eo, nullptr, H_SZ, E_SZ, 0, D_SZ,
                                           nullptr, nullptr, nullptr, nullptr);
    fused_gate_combine<<<B_SZ, 256>>>(x_in, Wg_0, bg_0, sewt, sews, eo, x1, x1h, 9, 0);

    // ---- layer 1 ----
    gemm_mma1<1,0><<<g1, 128, GEMM_SMEM>>>(x1h, w + 2*WT_ONE, b1_1,
                                           nullptr, h1, D_SZ, 9, 1, H_SZ,
                                           nullptr, nullptr, nullptr, nullptr);
    gemm_mma1<0,0><<<g2, 128, GEMM_SMEM>>>(h1, w + 3*WT_ONE, b2_1,
                                           eo, nullptr, H_SZ, E_SZ, 0, D_SZ,
                                           nullptr, nullptr, nullptr, nullptr);
    fused_gate_combine<<<B_SZ, 256>>>(x1, Wg_1, bg_1, sewt, sews, eo, out, nullptr, 8, 1);
}